// round 9
// baseline (speedup 1.0000x reference)
#include <cuda_runtime.h>
#include <cuda_fp16.h>
#include <cstdint>

#define N_NODES 200000
#define SEGS    16384
#define NTILES  ((N_NODES + 127) / 128)   // 1563
#define HEADS   4
#define LH2     68     // smem row stride in half2 units
#define LOUT    132    // f32 out-tile stride
#define SLOPE   0.01f

// ---------------- device scratch ----------------
__device__ float    g_alpha[N_NODES * HEADS];
__device__ float    g_e[N_NODES * HEADS];
__device__ unsigned g_amax[SEGS * HEADS];
__device__ float    g_denom[SEGS * HEADS];
__device__ unsigned g_pre1[HEADS * SEGS * 64];   // fp16x2: W1R . cry  per segment

// ---------------- helpers ----------------
__device__ __forceinline__ unsigned h2pack(float a, float b) {
    unsigned r;
    asm("cvt.rn.f16x2.f32 %0, %2, %1;" : "=r"(r) : "f"(a), "f"(b));
    return r;  // lo = a, hi = b
}

__device__ __forceinline__ void mma_f16(float c[4], const unsigned a[4], const unsigned b[2]) {
    asm volatile(
        "mma.sync.aligned.m16n8k16.row.col.f32.f16.f16.f32 "
        "{%0,%1,%2,%3}, {%4,%5,%6,%7}, {%8,%9}, {%0,%1,%2,%3};\n"
        : "+f"(c[0]), "+f"(c[1]), "+f"(c[2]), "+f"(c[3])
        : "r"(a[0]), "r"(a[1]), "r"(a[2]), "r"(a[3]), "r"(b[0]), "r"(b[1]));
}

__device__ __forceinline__ void cpa16(unsigned saddr, const void* g) {
    asm volatile("cp.async.ca.shared.global [%0], [%1], 16;" :: "r"(saddr), "l"(g) : "memory");
}

// 128x128x128 GEMM: C[r][o] += sum_k A[r][k]*B[o][k]; fp16 half2-packed smem,
// row stride LH2. 8 warps (4x2), warp tile 32x64. (R3-proven scalar-LDS feed.)
__device__ __forceinline__ void gemm128h(const unsigned* sA, const unsigned* sB,
                                         float (&acc)[2][8][4],
                                         int warpRow, int warpCol, int g, int t) {
#pragma unroll 4
    for (int ks = 0; ks < 8; ks++) {
        const int k0 = ks * 8;
        unsigned a[2][4], b[8][2];
#pragma unroll
        for (int mt = 0; mt < 2; mt++) {
            int r = warpRow * 32 + mt * 16 + g;
            a[mt][0] = sA[r * LH2 + k0 + t];
            a[mt][1] = sA[(r + 8) * LH2 + k0 + t];
            a[mt][2] = sA[r * LH2 + k0 + t + 4];
            a[mt][3] = sA[(r + 8) * LH2 + k0 + t + 4];
        }
#pragma unroll
        for (int nt = 0; nt < 8; nt++) {
            int o = warpCol * 64 + nt * 8 + g;
            b[nt][0] = sB[o * LH2 + k0 + t];
            b[nt][1] = sB[o * LH2 + k0 + t + 4];
        }
#pragma unroll
        for (int mt = 0; mt < 2; mt++)
#pragma unroll
            for (int nt = 0; nt < 8; nt++)
                mma_f16(acc[mt][nt], a[mt], b[nt]);
    }
}

// load [rows<=128,128] f32 -> fp16 smem tile (256 threads)
__device__ __forceinline__ void load_rows_h(unsigned* dst, const float* __restrict__ src,
                                            int rows, int tid) {
#pragma unroll
    for (int i = 0; i < 16; i++) {
        int v = i * 256 + tid;
        int r = v >> 5, c4 = v & 31;
        float4 val = make_float4(0.f, 0.f, 0.f, 0.f);
        if (r < rows) val = reinterpret_cast<const float4*>(src)[r * 32 + c4];
        uint2 u = make_uint2(h2pack(val.x, val.y), h2pack(val.z, val.w));
        *reinterpret_cast<uint2*>(dst + r * LH2 + c4 * 2) = u;
    }
}

__device__ __forceinline__ void load_w_h(unsigned* dst, const float* __restrict__ src,
                                         int srcStride, int tid) {
#pragma unroll
    for (int i = 0; i < 16; i++) {
        int v = i * 256 + tid;
        int r = v >> 5, c4 = v & 31;
        float4 val = *reinterpret_cast<const float4*>(src + (size_t)r * srcStride + c4 * 4);
        uint2 u = make_uint2(h2pack(val.x, val.y), h2pack(val.z, val.w));
        *reinterpret_cast<uint2*>(dst + r * LH2 + c4 * 2) = u;
    }
}

// ---------------- kernel 0: init ----------------
__global__ void k_init(float* __restrict__ out, int out_size) {
    int i = blockIdx.x * blockDim.x + threadIdx.x;
    int stride = gridDim.x * blockDim.x;
    int n4 = out_size >> 2;
    for (int j = i; j < n4; j += stride)
        reinterpret_cast<float4*>(out)[j] = make_float4(0.f, 0.f, 0.f, 0.f);
    for (int j = n4 * 4 + i; j < out_size; j += stride) out[j] = 0.f;
    for (int j = i; j < SEGS * HEADS; j += stride) {
        g_amax[j] = 0u;
        g_denom[j] = 0.f;
    }
}

// ---------------- kernel pre: pre1[h][s] = W1R . cry[s] (fp16) ----------------
__global__ void __launch_bounds__(256, 1)
k_pre(const float* __restrict__ cry, const float* __restrict__ Wa1) {
    extern __shared__ unsigned smem_u[];
    unsigned* sA = smem_u;              // cry tile
    unsigned* sB = sA + 128 * LH2;      // W1R

    const int tid  = threadIdx.x;
    const int lane = tid & 31;
    const int warp = tid >> 5;
    const int warpRow = warp >> 1, warpCol = warp & 1;
    const int g = lane >> 2, t = lane & 3;
    const int h  = blockIdx.y;
    const int s0 = blockIdx.x * 128;

    load_w_h(sB, Wa1 + (size_t)h * 128 * 256 + 128, 256, tid);
    load_w_h(sA, cry + (size_t)s0 * 128, 128, tid);
    __syncthreads();

    float acc[2][8][4];
#pragma unroll
    for (int x1 = 0; x1 < 2; x1++)
#pragma unroll
        for (int x2 = 0; x2 < 8; x2++)
#pragma unroll
            for (int x3 = 0; x3 < 4; x3++) acc[x1][x2][x3] = 0.f;
    gemm128h(sA, sB, acc, warpRow, warpCol, g, t);

#pragma unroll
    for (int mt = 0; mt < 2; mt++)
#pragma unroll
        for (int nt = 0; nt < 8; nt++)
#pragma unroll
            for (int j = 0; j < 2; j++) {
                int row = warpRow * 32 + mt * 16 + g + j * 8;
                int c0  = warpCol * 64 + nt * 8 + 2 * t;
                g_pre1[((size_t)h * SEGS + s0 + row) * 64 + (c0 >> 1)] =
                    h2pack(acc[mt][nt][j * 2 + 0], acc[mt][nt][j * 2 + 1]);
            }
}

// ---------------- kernel 1: alpha (single GEMM + gathered pre1) ----------------
__global__ void __launch_bounds__(256, 2)
k_alpha(const float* __restrict__ fea,
        const float* __restrict__ Wa1, const float* __restrict__ ba1,
        const float* __restrict__ Wa2, const float* __restrict__ ba2,
        const int* __restrict__ index) {
    extern __shared__ unsigned smem_u[];
    unsigned* sA   = smem_u;                  // fea tile
    unsigned* sB1  = sA + 128 * LH2;          // W1L
    unsigned* sPre = sB1 + 128 * LH2;         // gathered pre1 (fp16), stride LH2
    float* sb1   = (float*)(sPre + 128 * LH2);
    float* sw2   = sb1 + 128;
    float* sPart = sw2 + 128;                 // 256
    int*   sSeg  = (int*)(sPart + 256);       // 128

    const int tid  = threadIdx.x;
    const int lane = tid & 31;
    const int warp = tid >> 5;
    const int warpRow = warp >> 1, warpCol = warp & 1;
    const int g = lane >> 2, t = lane & 3;
    const int h = blockIdx.y;

    load_w_h(sB1, Wa1 + (size_t)h * 128 * 256, 256, tid);
    if (tid < 128) {
        sb1[tid] = ba1[h * 128 + tid];
        sw2[tid] = Wa2[h * 128 + tid];
    }
    const float ba2v = ba2[h];
    const unsigned sPreAddr = (unsigned)__cvta_generic_to_shared(sPre);
    const unsigned* preH = g_pre1 + (size_t)h * SEGS * 64;
    __syncthreads();

    for (int tile = blockIdx.x; tile < NTILES; tile += gridDim.x) {
        const int row0 = tile * 128;
        const int rows = min(128, N_NODES - row0);

        if (tid < 128) sSeg[tid] = (tid < rows) ? index[row0 + tid] : 0;
        load_rows_h(sA, fea + (size_t)row0 * 128, rows, tid);
        __syncthreads();

        // gather pre1 rows via cp.async (overlaps GEMM below)
#pragma unroll
        for (int i = 0; i < 8; i++) {
            int v = i * 256 + tid;
            int r = v >> 4, ch = v & 15;
            cpa16(sPreAddr + (unsigned)(r * LH2 + ch * 4) * 4,
                  preH + (size_t)sSeg[r] * 64 + ch * 4);
        }
        asm volatile("cp.async.commit_group;" ::: "memory");

        float acc[2][8][4];
#pragma unroll
        for (int x1 = 0; x1 < 2; x1++)
#pragma unroll
            for (int x2 = 0; x2 < 8; x2++)
#pragma unroll
                for (int x3 = 0; x3 < 4; x3++) acc[x1][x2][x3] = 0.f;
        gemm128h(sA, sB1, acc, warpRow, warpCol, g, t);

        asm volatile("cp.async.wait_group 0;" ::: "memory");
        __syncthreads();

        // alpha[r] = sum_o leaky(acc + pre[seg[r]][o] + b1[o]) * w2[o] + b2
        float p[2][2];
#pragma unroll
        for (int mt = 0; mt < 2; mt++) { p[mt][0] = 0.f; p[mt][1] = 0.f; }
#pragma unroll
        for (int mt = 0; mt < 2; mt++)
#pragma unroll
            for (int nt = 0; nt < 8; nt++) {
                const int c0 = warpCol * 64 + nt * 8 + 2 * t;
                const int rbase = warpRow * 32 + mt * 16 + g;
#pragma unroll
                for (int j = 0; j < 2; j++) {
                    unsigned pw = sPre[(rbase + j * 8) * LH2 + (c0 >> 1)];
                    float2 pf = __half22float2(*reinterpret_cast<__half2*>(&pw));
                    float x0 = acc[mt][nt][j * 2 + 0] + pf.x + sb1[c0];
                    float x1 = acc[mt][nt][j * 2 + 1] + pf.y + sb1[c0 + 1];
                    x0 = (x0 >= 0.f) ? x0 : SLOPE * x0;
                    x1 = (x1 >= 0.f) ? x1 : SLOPE * x1;
                    p[mt][j] += x0 * sw2[c0] + x1 * sw2[c0 + 1];
                }
            }
#pragma unroll
        for (int mt = 0; mt < 2; mt++)
#pragma unroll
            for (int j = 0; j < 2; j++) {
                float v = p[mt][j];
                v += __shfl_xor_sync(0xffffffffu, v, 1);
                v += __shfl_xor_sync(0xffffffffu, v, 2);
                if ((lane & 3) == 0)
                    sPart[(warpRow * 32 + mt * 16 + g + j * 8) * 2 + warpCol] = v;
            }
        __syncthreads();
        if (tid < rows)
            g_alpha[(size_t)(row0 + tid) * 4 + h] = sPart[tid * 2] + sPart[tid * 2 + 1] + ba2v;
        __syncthreads();
    }
}

// ---------------- kernels 2/3: softmax stats ----------------
__device__ __forceinline__ unsigned f2key(float f) {
    unsigned b = __float_as_uint(f);
    return (b & 0x80000000u) ? ~b : (b | 0x80000000u);
}
__device__ __forceinline__ float key2f(unsigned k) {
    return __uint_as_float((k & 0x80000000u) ? (k & 0x7fffffffu) : ~k);
}

__global__ void k_max(const int* __restrict__ index) {
    int i = blockIdx.x * blockDim.x + threadIdx.x;
    if (i >= N_NODES * HEADS) return;
    int n = i >> 2, h = i & 3;
    atomicMax(&g_amax[index[n] * 4 + h], f2key(g_alpha[i]));
}

__global__ void k_exp(const int* __restrict__ index) {
    int i = blockIdx.x * blockDim.x + threadIdx.x;
    if (i >= N_NODES * HEADS) return;
    int n = i >> 2, h = i & 3;
    int s = index[n] * 4 + h;
    float amax = key2f(g_amax[s]);
    float e = expf(g_alpha[i] - amax);
    g_e[i] = e;
    atomicAdd(&g_denom[s], e);
}

// ---------------- kernel 4: message MLP + weighted scatter-add (R3 body) -----
__global__ void __launch_bounds__(256, 1)
k_msg(const float* __restrict__ fea,
      const float* __restrict__ Wm1, const float* __restrict__ bm1,
      const float* __restrict__ Wm2, const float* __restrict__ bm2,
      const int* __restrict__ index, float* __restrict__ out) {
    extern __shared__ unsigned smem_u[];
    unsigned* sA  = smem_u;
    unsigned* sB1 = sA + 128 * LH2;
    unsigned* sB2 = sB1 + 128 * LH2;
    float* sOut   = (float*)(sB2 + 128 * LH2);   // 128*LOUT
    float* sb1    = sOut + 128 * LOUT;
    float* sb2    = sb1 + 128;
    float* sScale = sb2 + 128;
    int*   sSeg   = (int*)(sScale + 128);

    const int tid  = threadIdx.x;
    const int lane = tid & 31;
    const int warp = tid >> 5;
    const int warpRow = warp >> 1, warpCol = warp & 1;
    const int g = lane >> 2, t = lane & 3;
    const int h = blockIdx.y;

    load_w_h(sB1, Wm1 + (size_t)h * 128 * 128, 128, tid);
    load_w_h(sB2, Wm2 + (size_t)h * 128 * 128, 128, tid);
    if (tid < 128) {
        sb1[tid] = bm1[h * 128 + tid];
        sb2[tid] = bm2[h * 128 + tid];
    }
    __syncthreads();

    for (int tile = blockIdx.x; tile < NTILES; tile += gridDim.x) {
        const int row0 = tile * 128;
        const int rows = min(128, N_NODES - row0);

        if (tid < 128) {
            if (tid < rows) {
                int s = index[row0 + tid];
                sSeg[tid] = s;
                sScale[tid] = g_e[(size_t)(row0 + tid) * 4 + h] /
                              (g_denom[s * 4 + h] + 1e-16f);
            } else {
                sSeg[tid] = index[row0 + rows - 1];
                sScale[tid] = 0.f;
            }
        }
        load_rows_h(sA, fea + (size_t)row0 * 128, rows, tid);
        __syncthreads();

        float acc[2][8][4];
#pragma unroll
        for (int x1 = 0; x1 < 2; x1++)
#pragma unroll
            for (int x2 = 0; x2 < 8; x2++)
#pragma unroll
                for (int x3 = 0; x3 < 4; x3++) acc[x1][x2][x3] = 0.f;
        gemm128h(sA, sB1, acc, warpRow, warpCol, g, t);
        __syncthreads();

        // hidden = leaky(acc + b1) -> sA as fp16
#pragma unroll
        for (int mt = 0; mt < 2; mt++)
#pragma unroll
            for (int nt = 0; nt < 8; nt++)
#pragma unroll
                for (int ip = 0; ip < 2; ip++) {
                    int row = warpRow * 32 + mt * 16 + g + ip * 8;
                    int c0 = warpCol * 64 + nt * 8 + 2 * t;
                    float x0 = acc[mt][nt][ip * 2 + 0] + sb1[c0];
                    float x1 = acc[mt][nt][ip * 2 + 1] + sb1[c0 + 1];
                    x0 = (x0 >= 0.f) ? x0 : SLOPE * x0;
                    x1 = (x1 >= 0.f) ? x1 : SLOPE * x1;
                    sA[row * LH2 + warpCol * 32 + nt * 4 + t] = h2pack(x0, x1);
                }
        __syncthreads();

#pragma unroll
        for (int x1 = 0; x1 < 2; x1++)
#pragma unroll
            for (int x2 = 0; x2 < 8; x2++)
#pragma unroll
                for (int x3 = 0; x3 < 4; x3++) acc[x1][x2][x3] = 0.f;
        gemm128h(sA, sB2, acc, warpRow, warpCol, g, t);

        // m*alpha -> sOut (fp32)
#pragma unroll
        for (int mt = 0; mt < 2; mt++)
#pragma unroll
            for (int nt = 0; nt < 8; nt++)
#pragma unroll
                for (int ip = 0; ip < 2; ip++) {
                    int row = warpRow * 32 + mt * 16 + g + ip * 8;
                    int c0 = warpCol * 64 + nt * 8 + 2 * t;
                    float sc = sScale[row];
                    float2 v;
                    v.x = (acc[mt][nt][ip * 2 + 0] + sb2[c0]) * sc;
                    v.y = (acc[mt][nt][ip * 2 + 1] + sb2[c0 + 1]) * sc;
                    *reinterpret_cast<float2*>(sOut + row * LOUT + c0) = v;
                }
        __syncthreads();

        // segmented reduce (sorted index): thread = column, two row-halves
        {
            const int c = tid & 127;
            const int r0 = (tid >> 7) * 64;
            float accum = 0.f;
            int cur = sSeg[r0];
            for (int r = r0; r < r0 + 64; r++) {
                int s = sSeg[r];
                if (s != cur) {
                    atomicAdd(&out[(size_t)cur * 512 + h * 128 + c], accum);
                    accum = 0.f;
                    cur = s;
                }
                accum += sOut[r * LOUT + c];
            }
            atomicAdd(&out[(size_t)cur * 512 + h * 128 + c], accum);
        }
        __syncthreads();
    }
}

// ---------------- launch ----------------
extern "C" void kernel_launch(void* const* d_in, const int* in_sizes, int n_in,
                              void* d_out, int out_size) {
    (void)in_sizes; (void)n_in;
    const float* fea = (const float*)d_in[0];
    const float* cry = (const float*)d_in[1];
    const float* Wm1 = (const float*)d_in[2];
    const float* bm1 = (const float*)d_in[3];
    const float* Wm2 = (const float*)d_in[4];
    const float* bm2 = (const float*)d_in[5];
    const float* Wa1 = (const float*)d_in[6];
    const float* ba1 = (const float*)d_in[7];
    const float* Wa2 = (const float*)d_in[8];
    const float* ba2 = (const float*)d_in[9];
    const int*   idx = (const int*)d_in[10];
    float* out = (float*)d_out;

    const size_t smem_pre   = (size_t)(2 * 128 * LH2) * 4;
    const size_t smem_alpha = (size_t)(3 * 128 * LH2 + 128 + 128 + 256 + 128) * 4;
    const size_t smem_msg   = (size_t)(3 * 128 * LH2 + 128 * LOUT + 128 + 128 + 128 + 128) * 4;
    cudaFuncSetAttribute(k_pre,   cudaFuncAttributeMaxDynamicSharedMemorySize, (int)smem_pre);
    cudaFuncSetAttribute(k_alpha, cudaFuncAttributeMaxDynamicSharedMemorySize, (int)smem_alpha);
    cudaFuncSetAttribute(k_msg,   cudaFuncAttributeMaxDynamicSharedMemorySize, (int)smem_msg);

    k_init<<<2048, 512>>>(out, out_size);
    k_pre<<<dim3(SEGS / 128, 4), 256, smem_pre>>>(cry, Wa1);
    k_alpha<<<dim3(74, 4), 256, smem_alpha>>>(fea, Wa1, ba1, Wa2, ba2, idx);
    int total = N_NODES * HEADS;
    k_max<<<(total + 255) / 256, 256>>>(idx);
    k_exp<<<(total + 255) / 256, 256>>>(idx);
    k_msg<<<dim3(37, 4), 256, smem_msg>>>(fea, Wm1, bm1, Wm2, bm2, idx, out);
}

// round 10
// speedup vs baseline: 1.2057x; 1.2057x over previous
#include <cuda_runtime.h>
#include <cuda_fp16.h>
#include <cstdint>

#define N_NODES 200000
#define SEGS    16384
#define NTILES  ((N_NODES + 127) / 128)   // 1563
#define HEADS   4
#define LH2     68     // smem row stride in half2 units
#define LOUT    132    // f32 out-tile stride
#define SLOPE   0.01f

// ---------------- device scratch ----------------
__device__ float    g_alpha[N_NODES * HEADS];
__device__ float    g_e[N_NODES * HEADS];
__device__ unsigned g_amax[SEGS * HEADS];
__device__ float    g_denom[SEGS * HEADS];
__device__ unsigned g_pre1[HEADS * SEGS * 64];   // fp16x2: W1R . cry  per segment

// ---------------- helpers ----------------
__device__ __forceinline__ unsigned h2pack(float a, float b) {
    unsigned r;
    asm("cvt.rn.f16x2.f32 %0, %2, %1;" : "=r"(r) : "f"(a), "f"(b));
    return r;  // lo = a, hi = b
}

__device__ __forceinline__ void mma_f16(float c[4], const unsigned a[4], const unsigned b[2]) {
    asm volatile(
        "mma.sync.aligned.m16n8k16.row.col.f32.f16.f16.f32 "
        "{%0,%1,%2,%3}, {%4,%5,%6,%7}, {%8,%9}, {%0,%1,%2,%3};\n"
        : "+f"(c[0]), "+f"(c[1]), "+f"(c[2]), "+f"(c[3])
        : "r"(a[0]), "r"(a[1]), "r"(a[2]), "r"(a[3]), "r"(b[0]), "r"(b[1]));
}

__device__ __forceinline__ void cpa16(unsigned saddr, const void* g) {
    asm volatile("cp.async.ca.shared.global [%0], [%1], 16;" :: "r"(saddr), "l"(g) : "memory");
}

// 128x128x128 GEMM: C[r][o] += sum_k A[r][k]*B[o][k]; fp16 half2-packed smem,
// row stride LH2. 8 warps (4x2), warp tile 32x64.
__device__ __forceinline__ void gemm128h(const unsigned* sA, const unsigned* sB,
                                         float (&acc)[2][8][4],
                                         int warpRow, int warpCol, int g, int t) {
#pragma unroll 4
    for (int ks = 0; ks < 8; ks++) {
        const int k0 = ks * 8;
        unsigned a[2][4], b[8][2];
#pragma unroll
        for (int mt = 0; mt < 2; mt++) {
            int r = warpRow * 32 + mt * 16 + g;
            a[mt][0] = sA[r * LH2 + k0 + t];
            a[mt][1] = sA[(r + 8) * LH2 + k0 + t];
            a[mt][2] = sA[r * LH2 + k0 + t + 4];
            a[mt][3] = sA[(r + 8) * LH2 + k0 + t + 4];
        }
#pragma unroll
        for (int nt = 0; nt < 8; nt++) {
            int o = warpCol * 64 + nt * 8 + g;
            b[nt][0] = sB[o * LH2 + k0 + t];
            b[nt][1] = sB[o * LH2 + k0 + t + 4];
        }
#pragma unroll
        for (int mt = 0; mt < 2; mt++)
#pragma unroll
            for (int nt = 0; nt < 8; nt++)
                mma_f16(acc[mt][nt], a[mt], b[nt]);
    }
}

// load [rows<=128,128] f32 -> fp16 smem tile (256 threads)
__device__ __forceinline__ void load_rows_h(unsigned* dst, const float* __restrict__ src,
                                            int rows, int tid) {
#pragma unroll
    for (int i = 0; i < 16; i++) {
        int v = i * 256 + tid;
        int r = v >> 5, c4 = v & 31;
        float4 val = make_float4(0.f, 0.f, 0.f, 0.f);
        if (r < rows) val = reinterpret_cast<const float4*>(src)[r * 32 + c4];
        uint2 u = make_uint2(h2pack(val.x, val.y), h2pack(val.z, val.w));
        *reinterpret_cast<uint2*>(dst + r * LH2 + c4 * 2) = u;
    }
}

__device__ __forceinline__ void load_w_h(unsigned* dst, const float* __restrict__ src,
                                         int srcStride, int tid) {
#pragma unroll
    for (int i = 0; i < 16; i++) {
        int v = i * 256 + tid;
        int r = v >> 5, c4 = v & 31;
        float4 val = *reinterpret_cast<const float4*>(src + (size_t)r * srcStride + c4 * 4);
        uint2 u = make_uint2(h2pack(val.x, val.y), h2pack(val.z, val.w));
        *reinterpret_cast<uint2*>(dst + r * LH2 + c4 * 2) = u;
    }
}

// ---------------- kernel 0: init ----------------
__global__ void k_init(float* __restrict__ out, int out_size) {
    int i = blockIdx.x * blockDim.x + threadIdx.x;
    int stride = gridDim.x * blockDim.x;
    int n4 = out_size >> 2;
    for (int j = i; j < n4; j += stride)
        reinterpret_cast<float4*>(out)[j] = make_float4(0.f, 0.f, 0.f, 0.f);
    for (int j = n4 * 4 + i; j < out_size; j += stride) out[j] = 0.f;
    for (int j = i; j < SEGS * HEADS; j += stride) {
        g_amax[j] = 0u;
        g_denom[j] = 0.f;
    }
}

// ---------------- kernel pre: pre1[h][s] = W1R . cry[s] (fp16) ----------------
__global__ void __launch_bounds__(256, 1)
k_pre(const float* __restrict__ cry, const float* __restrict__ Wa1) {
    extern __shared__ unsigned smem_u[];
    unsigned* sA = smem_u;              // cry tile
    unsigned* sB = sA + 128 * LH2;      // W1R

    const int tid  = threadIdx.x;
    const int lane = tid & 31;
    const int warp = tid >> 5;
    const int warpRow = warp >> 1, warpCol = warp & 1;
    const int g = lane >> 2, t = lane & 3;
    const int h  = blockIdx.y;
    const int s0 = blockIdx.x * 128;

    load_w_h(sB, Wa1 + (size_t)h * 128 * 256 + 128, 256, tid);
    load_w_h(sA, cry + (size_t)s0 * 128, 128, tid);
    __syncthreads();

    float acc[2][8][4];
#pragma unroll
    for (int x1 = 0; x1 < 2; x1++)
#pragma unroll
        for (int x2 = 0; x2 < 8; x2++)
#pragma unroll
            for (int x3 = 0; x3 < 4; x3++) acc[x1][x2][x3] = 0.f;
    gemm128h(sA, sB, acc, warpRow, warpCol, g, t);

#pragma unroll
    for (int mt = 0; mt < 2; mt++)
#pragma unroll
        for (int nt = 0; nt < 8; nt++)
#pragma unroll
            for (int j = 0; j < 2; j++) {
                int row = warpRow * 32 + mt * 16 + g + j * 8;
                int c0  = warpCol * 64 + nt * 8 + 2 * t;
                g_pre1[((size_t)h * SEGS + s0 + row) * 64 + (c0 >> 1)] =
                    h2pack(acc[mt][nt][j * 2 + 0], acc[mt][nt][j * 2 + 1]);
            }
}

// ---------------- kernel 1: alpha (single GEMM + gathered pre1) ----------------
__global__ void __launch_bounds__(256, 2)
k_alpha(const float* __restrict__ fea,
        const float* __restrict__ Wa1, const float* __restrict__ ba1,
        const float* __restrict__ Wa2, const float* __restrict__ ba2,
        const int* __restrict__ index) {
    extern __shared__ unsigned smem_u[];
    unsigned* sA   = smem_u;                  // fea tile
    unsigned* sB1  = sA + 128 * LH2;          // W1L
    unsigned* sPre = sB1 + 128 * LH2;         // gathered pre1 (fp16), stride LH2
    float* sb1   = (float*)(sPre + 128 * LH2);
    float* sw2   = sb1 + 128;
    float* sPart = sw2 + 128;                 // 256
    int*   sSeg  = (int*)(sPart + 256);       // 128

    const int tid  = threadIdx.x;
    const int lane = tid & 31;
    const int warp = tid >> 5;
    const int warpRow = warp >> 1, warpCol = warp & 1;
    const int g = lane >> 2, t = lane & 3;
    const int h = blockIdx.y;

    load_w_h(sB1, Wa1 + (size_t)h * 128 * 256, 256, tid);
    if (tid < 128) {
        sb1[tid] = ba1[h * 128 + tid];
        sw2[tid] = Wa2[h * 128 + tid];
    }
    const float ba2v = ba2[h];
    const unsigned sPreAddr = (unsigned)__cvta_generic_to_shared(sPre);
    const unsigned* preH = g_pre1 + (size_t)h * SEGS * 64;
    __syncthreads();

    for (int tile = blockIdx.x; tile < NTILES; tile += gridDim.x) {
        const int row0 = tile * 128;
        const int rows = min(128, N_NODES - row0);

        if (tid < 128) sSeg[tid] = (tid < rows) ? index[row0 + tid] : 0;
        load_rows_h(sA, fea + (size_t)row0 * 128, rows, tid);
        __syncthreads();

        // gather pre1 rows via cp.async (overlaps GEMM below)
#pragma unroll
        for (int i = 0; i < 8; i++) {
            int v = i * 256 + tid;
            int r = v >> 4, ch = v & 15;
            cpa16(sPreAddr + (unsigned)(r * LH2 + ch * 4) * 4,
                  preH + (size_t)sSeg[r] * 64 + ch * 4);
        }
        asm volatile("cp.async.commit_group;" ::: "memory");

        float acc[2][8][4];
#pragma unroll
        for (int x1 = 0; x1 < 2; x1++)
#pragma unroll
            for (int x2 = 0; x2 < 8; x2++)
#pragma unroll
                for (int x3 = 0; x3 < 4; x3++) acc[x1][x2][x3] = 0.f;
        gemm128h(sA, sB1, acc, warpRow, warpCol, g, t);

        asm volatile("cp.async.wait_group 0;" ::: "memory");
        __syncthreads();

        // alpha[r] = sum_o leaky(acc + pre[seg[r]][o] + b1[o]) * w2[o] + b2
        float p[2][2];
#pragma unroll
        for (int mt = 0; mt < 2; mt++) { p[mt][0] = 0.f; p[mt][1] = 0.f; }
#pragma unroll
        for (int mt = 0; mt < 2; mt++)
#pragma unroll
            for (int nt = 0; nt < 8; nt++) {
                const int c0 = warpCol * 64 + nt * 8 + 2 * t;
                const int rbase = warpRow * 32 + mt * 16 + g;
#pragma unroll
                for (int j = 0; j < 2; j++) {
                    unsigned pw = sPre[(rbase + j * 8) * LH2 + (c0 >> 1)];
                    float2 pf = __half22float2(*reinterpret_cast<__half2*>(&pw));
                    float x0 = acc[mt][nt][j * 2 + 0] + pf.x + sb1[c0];
                    float x1 = acc[mt][nt][j * 2 + 1] + pf.y + sb1[c0 + 1];
                    x0 = (x0 >= 0.f) ? x0 : SLOPE * x0;
                    x1 = (x1 >= 0.f) ? x1 : SLOPE * x1;
                    p[mt][j] += x0 * sw2[c0] + x1 * sw2[c0 + 1];
                }
            }
#pragma unroll
        for (int mt = 0; mt < 2; mt++)
#pragma unroll
            for (int j = 0; j < 2; j++) {
                float v = p[mt][j];
                v += __shfl_xor_sync(0xffffffffu, v, 1);
                v += __shfl_xor_sync(0xffffffffu, v, 2);
                if ((lane & 3) == 0)
                    sPart[(warpRow * 32 + mt * 16 + g + j * 8) * 2 + warpCol] = v;
            }
        __syncthreads();
        if (tid < rows)
            g_alpha[(size_t)(row0 + tid) * 4 + h] = sPart[tid * 2] + sPart[tid * 2 + 1] + ba2v;
        __syncthreads();
    }
}

// ---------------- kernels 2/3: softmax stats ----------------
__device__ __forceinline__ unsigned f2key(float f) {
    unsigned b = __float_as_uint(f);
    return (b & 0x80000000u) ? ~b : (b | 0x80000000u);
}
__device__ __forceinline__ float key2f(unsigned k) {
    return __uint_as_float((k & 0x80000000u) ? (k & 0x7fffffffu) : ~k);
}

__global__ void k_max(const int* __restrict__ index) {
    int i = blockIdx.x * blockDim.x + threadIdx.x;
    if (i >= N_NODES * HEADS) return;
    int n = i >> 2, h = i & 3;
    atomicMax(&g_amax[index[n] * 4 + h], f2key(g_alpha[i]));
}

__global__ void k_exp(const int* __restrict__ index) {
    int i = blockIdx.x * blockDim.x + threadIdx.x;
    if (i >= N_NODES * HEADS) return;
    int n = i >> 2, h = i & 3;
    int s = index[n] * 4 + h;
    float amax = key2f(g_amax[s]);
    float e = expf(g_alpha[i] - amax);
    g_e[i] = e;
    atomicAdd(&g_denom[s], e);
}

// ---------------- kernel 4: message MLP + weighted scatter-add --------------
// occupancy 2: sOut (64 rows, f32) reuses the sA tile space after GEMM2.
__global__ void __launch_bounds__(256, 2)
k_msg(const float* __restrict__ fea,
      const float* __restrict__ Wm1, const float* __restrict__ bm1,
      const float* __restrict__ Wm2, const float* __restrict__ bm2,
      const int* __restrict__ index, float* __restrict__ out) {
    extern __shared__ unsigned smem_u[];
    unsigned* sA  = smem_u;                    // fea/hidden tile; later sOut
    unsigned* sB1 = sA + 128 * LH2;
    unsigned* sB2 = sB1 + 128 * LH2;
    float* sb1    = (float*)(sB2 + 128 * LH2);
    float* sb2    = sb1 + 128;
    float* sScale = sb2 + 128;
    int*   sSeg   = (int*)(sScale + 128);
    float* sOut   = (float*)sA;                // [64][LOUT] f32, reuses sA

    const int tid  = threadIdx.x;
    const int lane = tid & 31;
    const int warp = tid >> 5;
    const int warpRow = warp >> 1, warpCol = warp & 1;
    const int g = lane >> 2, t = lane & 3;
    const int h = blockIdx.y;

    load_w_h(sB1, Wm1 + (size_t)h * 128 * 128, 128, tid);
    load_w_h(sB2, Wm2 + (size_t)h * 128 * 128, 128, tid);
    if (tid < 128) {
        sb1[tid] = bm1[h * 128 + tid];
        sb2[tid] = bm2[h * 128 + tid];
    }
    __syncthreads();

    for (int tile = blockIdx.x; tile < NTILES; tile += gridDim.x) {
        const int row0 = tile * 128;
        const int rows = min(128, N_NODES - row0);

        if (tid < 128) {
            if (tid < rows) {
                int s = index[row0 + tid];
                sSeg[tid] = s;
                sScale[tid] = g_e[(size_t)(row0 + tid) * 4 + h] /
                              (g_denom[s * 4 + h] + 1e-16f);
            } else {
                sSeg[tid] = index[row0 + rows - 1];
                sScale[tid] = 0.f;
            }
        }
        load_rows_h(sA, fea + (size_t)row0 * 128, rows, tid);
        __syncthreads();

        float acc[2][8][4];
#pragma unroll
        for (int x1 = 0; x1 < 2; x1++)
#pragma unroll
            for (int x2 = 0; x2 < 8; x2++)
#pragma unroll
                for (int x3 = 0; x3 < 4; x3++) acc[x1][x2][x3] = 0.f;
        gemm128h(sA, sB1, acc, warpRow, warpCol, g, t);
        __syncthreads();

        // hidden = leaky(acc + b1) -> sA as fp16
#pragma unroll
        for (int mt = 0; mt < 2; mt++)
#pragma unroll
            for (int nt = 0; nt < 8; nt++)
#pragma unroll
                for (int ip = 0; ip < 2; ip++) {
                    int row = warpRow * 32 + mt * 16 + g + ip * 8;
                    int c0 = warpCol * 64 + nt * 8 + 2 * t;
                    float x0 = acc[mt][nt][ip * 2 + 0] + sb1[c0];
                    float x1 = acc[mt][nt][ip * 2 + 1] + sb1[c0 + 1];
                    x0 = (x0 >= 0.f) ? x0 : SLOPE * x0;
                    x1 = (x1 >= 0.f) ? x1 : SLOPE * x1;
                    sA[row * LH2 + warpCol * 32 + nt * 4 + t] = h2pack(x0, x1);
                }
        __syncthreads();

#pragma unroll
        for (int x1 = 0; x1 < 2; x1++)
#pragma unroll
            for (int x2 = 0; x2 < 8; x2++)
#pragma unroll
                for (int x3 = 0; x3 < 4; x3++) acc[x1][x2][x3] = 0.f;
        gemm128h(sA, sB2, acc, warpRow, warpCol, g, t);
        __syncthreads();   // all reads of hidden done; sA reusable as sOut

        // epilogue: two 64-row passes through sOut (reused sA space)
#pragma unroll
        for (int pass = 0; pass < 2; pass++) {
            if ((warpRow >> 1) == pass) {      // warps owning rows pass*64..+63
#pragma unroll
                for (int mt = 0; mt < 2; mt++)
#pragma unroll
                    for (int nt = 0; nt < 8; nt++)
#pragma unroll
                        for (int ip = 0; ip < 2; ip++) {
                            int row  = warpRow * 32 + mt * 16 + g + ip * 8;
                            int lrow = (warpRow & 1) * 32 + mt * 16 + g + ip * 8;
                            int c0 = warpCol * 64 + nt * 8 + 2 * t;
                            float sc = sScale[row];
                            float2 v;
                            v.x = (acc[mt][nt][ip * 2 + 0] + sb2[c0]) * sc;
                            v.y = (acc[mt][nt][ip * 2 + 1] + sb2[c0 + 1]) * sc;
                            *reinterpret_cast<float2*>(sOut + lrow * LOUT + c0) = v;
                        }
            }
            __syncthreads();
            {
                const int c = tid & 127;
                const int lr0 = (tid >> 7) * 32;          // 0 or 32 (local)
                const int gr0 = pass * 64 + lr0;          // global row base
                float accum = 0.f;
                int cur = sSeg[gr0];
                for (int r = 0; r < 32; r++) {
                    int s = sSeg[gr0 + r];
                    if (s != cur) {
                        atomicAdd(&out[(size_t)cur * 512 + h * 128 + c], accum);
                        accum = 0.f;
                        cur = s;
                    }
                    accum += sOut[(lr0 + r) * LOUT + c];
                }
                atomicAdd(&out[(size_t)cur * 512 + h * 128 + c], accum);
            }
            __syncthreads();
        }
    }
}

// ---------------- launch ----------------
extern "C" void kernel_launch(void* const* d_in, const int* in_sizes, int n_in,
                              void* d_out, int out_size) {
    (void)in_sizes; (void)n_in;
    const float* fea = (const float*)d_in[0];
    const float* cry = (const float*)d_in[1];
    const float* Wm1 = (const float*)d_in[2];
    const float* bm1 = (const float*)d_in[3];
    const float* Wm2 = (const float*)d_in[4];
    const float* bm2 = (const float*)d_in[5];
    const float* Wa1 = (const float*)d_in[6];
    const float* ba1 = (const float*)d_in[7];
    const float* Wa2 = (const float*)d_in[8];
    const float* ba2 = (const float*)d_in[9];
    const int*   idx = (const int*)d_in[10];
    float* out = (float*)d_out;

    const size_t smem_pre   = (size_t)(2 * 128 * LH2) * 4;
    const size_t smem_alpha = (size_t)(3 * 128 * LH2 + 128 + 128 + 256 + 128) * 4;
    const size_t smem_msg   = (size_t)(3 * 128 * LH2 + 128 + 128 + 128 + 128) * 4;
    cudaFuncSetAttribute(k_pre,   cudaFuncAttributeMaxDynamicSharedMemorySize, (int)smem_pre);
    cudaFuncSetAttribute(k_alpha, cudaFuncAttributeMaxDynamicSharedMemorySize, (int)smem_alpha);
    cudaFuncSetAttribute(k_msg,   cudaFuncAttributeMaxDynamicSharedMemorySize, (int)smem_msg);

    k_init<<<2048, 512>>>(out, out_size);
    k_pre<<<dim3(SEGS / 128, 4), 256, smem_pre>>>(cry, Wa1);
    k_alpha<<<dim3(74, 4), 256, smem_alpha>>>(fea, Wa1, ba1, Wa2, ba2, idx);
    int total = N_NODES * HEADS;
    k_max<<<(total + 255) / 256, 256>>>(idx);
    k_exp<<<(total + 255) / 256, 256>>>(idx);
    k_msg<<<dim3(74, 4), 256, smem_msg>>>(fea, Wm1, bm1, Wm2, bm2, idx, out);
}

// round 11
// speedup vs baseline: 1.3612x; 1.1290x over previous
#include <cuda_runtime.h>
#include <cuda_fp16.h>
#include <cstdint>

#define N_NODES 200000
#define SEGS    16384
#define NTILES  ((N_NODES + 127) / 128)   // 1563
#define HEADS   4
#define LH2     68     // smem row stride in half2 units
#define LOUT    132    // f32 out-tile stride
#define SLOPE   0.01f

// ---------------- device scratch ----------------
__device__ float    g_alpha[N_NODES * HEADS];
__device__ float    g_e[N_NODES * HEADS];
__device__ unsigned g_amax[SEGS * HEADS];
__device__ float    g_denom[SEGS * HEADS];
__device__ unsigned g_pre1[HEADS * SEGS * 64];   // fp16x2: W1R . cry  per segment
__device__ float    g_H[(size_t)HEADS * SEGS * 128];  // Σ α_n h_n per segment

// ---------------- helpers ----------------
__device__ __forceinline__ unsigned h2pack(float a, float b) {
    unsigned r;
    asm("cvt.rn.f16x2.f32 %0, %2, %1;" : "=r"(r) : "f"(a), "f"(b));
    return r;  // lo = a, hi = b
}

__device__ __forceinline__ void mma_f16(float c[4], const unsigned a[4], const unsigned b[2]) {
    asm volatile(
        "mma.sync.aligned.m16n8k16.row.col.f32.f16.f16.f32 "
        "{%0,%1,%2,%3}, {%4,%5,%6,%7}, {%8,%9}, {%0,%1,%2,%3};\n"
        : "+f"(c[0]), "+f"(c[1]), "+f"(c[2]), "+f"(c[3])
        : "r"(a[0]), "r"(a[1]), "r"(a[2]), "r"(a[3]), "r"(b[0]), "r"(b[1]));
}

__device__ __forceinline__ void cpa16(unsigned saddr, const void* g) {
    asm volatile("cp.async.ca.shared.global [%0], [%1], 16;" :: "r"(saddr), "l"(g) : "memory");
}

// 128x128x128 GEMM: C[r][o] += sum_k A[r][k]*B[o][k]; fp16 half2-packed smem,
// row stride LH2. 8 warps (4x2), warp tile 32x64.
__device__ __forceinline__ void gemm128h(const unsigned* sA, const unsigned* sB,
                                         float (&acc)[2][8][4],
                                         int warpRow, int warpCol, int g, int t) {
#pragma unroll 4
    for (int ks = 0; ks < 8; ks++) {
        const int k0 = ks * 8;
        unsigned a[2][4], b[8][2];
#pragma unroll
        for (int mt = 0; mt < 2; mt++) {
            int r = warpRow * 32 + mt * 16 + g;
            a[mt][0] = sA[r * LH2 + k0 + t];
            a[mt][1] = sA[(r + 8) * LH2 + k0 + t];
            a[mt][2] = sA[r * LH2 + k0 + t + 4];
            a[mt][3] = sA[(r + 8) * LH2 + k0 + t + 4];
        }
#pragma unroll
        for (int nt = 0; nt < 8; nt++) {
            int o = warpCol * 64 + nt * 8 + g;
            b[nt][0] = sB[o * LH2 + k0 + t];
            b[nt][1] = sB[o * LH2 + k0 + t + 4];
        }
#pragma unroll
        for (int mt = 0; mt < 2; mt++)
#pragma unroll
            for (int nt = 0; nt < 8; nt++)
                mma_f16(acc[mt][nt], a[mt], b[nt]);
    }
}

// load [rows<=128,128] f32 -> fp16 smem tile (256 threads)
__device__ __forceinline__ void load_rows_h(unsigned* dst, const float* __restrict__ src,
                                            int rows, int tid) {
#pragma unroll
    for (int i = 0; i < 16; i++) {
        int v = i * 256 + tid;
        int r = v >> 5, c4 = v & 31;
        float4 val = make_float4(0.f, 0.f, 0.f, 0.f);
        if (r < rows) val = reinterpret_cast<const float4*>(src)[r * 32 + c4];
        uint2 u = make_uint2(h2pack(val.x, val.y), h2pack(val.z, val.w));
        *reinterpret_cast<uint2*>(dst + r * LH2 + c4 * 2) = u;
    }
}

__device__ __forceinline__ void load_w_h(unsigned* dst, const float* __restrict__ src,
                                         int srcStride, int tid) {
#pragma unroll
    for (int i = 0; i < 16; i++) {
        int v = i * 256 + tid;
        int r = v >> 5, c4 = v & 31;
        float4 val = *reinterpret_cast<const float4*>(src + (size_t)r * srcStride + c4 * 4);
        uint2 u = make_uint2(h2pack(val.x, val.y), h2pack(val.z, val.w));
        *reinterpret_cast<uint2*>(dst + r * LH2 + c4 * 2) = u;
    }
}

// ---------------- kernel 0: init (zero g_H + softmax stats) ----------------
__global__ void k_init() {
    int i = blockIdx.x * blockDim.x + threadIdx.x;
    int stride = gridDim.x * blockDim.x;
    int n4 = (HEADS * SEGS * 128) >> 2;
    for (int j = i; j < n4; j += stride)
        reinterpret_cast<float4*>(g_H)[j] = make_float4(0.f, 0.f, 0.f, 0.f);
    for (int j = i; j < SEGS * HEADS; j += stride) {
        g_amax[j] = 0u;
        g_denom[j] = 0.f;
    }
}

// ---------------- kernel pre: pre1[h][s] = W1R . cry[s] (fp16) ----------------
__global__ void __launch_bounds__(256, 1)
k_pre(const float* __restrict__ cry, const float* __restrict__ Wa1) {
    extern __shared__ unsigned smem_u[];
    unsigned* sA = smem_u;              // cry tile
    unsigned* sB = sA + 128 * LH2;      // W1R

    const int tid  = threadIdx.x;
    const int lane = tid & 31;
    const int warp = tid >> 5;
    const int warpRow = warp >> 1, warpCol = warp & 1;
    const int g = lane >> 2, t = lane & 3;
    const int h  = blockIdx.y;
    const int s0 = blockIdx.x * 128;

    load_w_h(sB, Wa1 + (size_t)h * 128 * 256 + 128, 256, tid);
    load_w_h(sA, cry + (size_t)s0 * 128, 128, tid);
    __syncthreads();

    float acc[2][8][4];
#pragma unroll
    for (int x1 = 0; x1 < 2; x1++)
#pragma unroll
        for (int x2 = 0; x2 < 8; x2++)
#pragma unroll
            for (int x3 = 0; x3 < 4; x3++) acc[x1][x2][x3] = 0.f;
    gemm128h(sA, sB, acc, warpRow, warpCol, g, t);

#pragma unroll
    for (int mt = 0; mt < 2; mt++)
#pragma unroll
        for (int nt = 0; nt < 8; nt++)
#pragma unroll
            for (int j = 0; j < 2; j++) {
                int row = warpRow * 32 + mt * 16 + g + j * 8;
                int c0  = warpCol * 64 + nt * 8 + 2 * t;
                g_pre1[((size_t)h * SEGS + s0 + row) * 64 + (c0 >> 1)] =
                    h2pack(acc[mt][nt][j * 2 + 0], acc[mt][nt][j * 2 + 1]);
            }
}

// ---------------- softmax key helpers ----------------
__device__ __forceinline__ unsigned f2key(float f) {
    unsigned b = __float_as_uint(f);
    return (b & 0x80000000u) ? ~b : (b | 0x80000000u);
}
__device__ __forceinline__ float key2f(unsigned k) {
    return __uint_as_float((k & 0x80000000u) ? (k & 0x7fffffffu) : ~k);
}

// ---------------- kernel 1: alpha (single GEMM + gathered pre1 + fused max) --
__global__ void __launch_bounds__(256, 2)
k_alpha(const float* __restrict__ fea,
        const float* __restrict__ Wa1, const float* __restrict__ ba1,
        const float* __restrict__ Wa2, const float* __restrict__ ba2,
        const int* __restrict__ index) {
    extern __shared__ unsigned smem_u[];
    unsigned* sA   = smem_u;                  // fea tile
    unsigned* sB1  = sA + 128 * LH2;          // W1L
    unsigned* sPre = sB1 + 128 * LH2;         // gathered pre1 (fp16), stride LH2
    float* sb1   = (float*)(sPre + 128 * LH2);
    float* sw2   = sb1 + 128;
    float* sPart = sw2 + 128;                 // 256
    int*   sSeg  = (int*)(sPart + 256);       // 128

    const int tid  = threadIdx.x;
    const int lane = tid & 31;
    const int warp = tid >> 5;
    const int warpRow = warp >> 1, warpCol = warp & 1;
    const int g = lane >> 2, t = lane & 3;
    const int h = blockIdx.y;

    load_w_h(sB1, Wa1 + (size_t)h * 128 * 256, 256, tid);
    if (tid < 128) {
        sb1[tid] = ba1[h * 128 + tid];
        sw2[tid] = Wa2[h * 128 + tid];
    }
    const float ba2v = ba2[h];
    const unsigned sPreAddr = (unsigned)__cvta_generic_to_shared(sPre);
    const unsigned* preH = g_pre1 + (size_t)h * SEGS * 64;
    __syncthreads();

    for (int tile = blockIdx.x; tile < NTILES; tile += gridDim.x) {
        const int row0 = tile * 128;
        const int rows = min(128, N_NODES - row0);

        if (tid < 128) sSeg[tid] = (tid < rows) ? index[row0 + tid] : 0;
        load_rows_h(sA, fea + (size_t)row0 * 128, rows, tid);
        __syncthreads();

        // gather pre1 rows via cp.async (overlaps GEMM below)
#pragma unroll
        for (int i = 0; i < 8; i++) {
            int v = i * 256 + tid;
            int r = v >> 4, ch = v & 15;
            cpa16(sPreAddr + (unsigned)(r * LH2 + ch * 4) * 4,
                  preH + (size_t)sSeg[r] * 64 + ch * 4);
        }
        asm volatile("cp.async.commit_group;" ::: "memory");

        float acc[2][8][4];
#pragma unroll
        for (int x1 = 0; x1 < 2; x1++)
#pragma unroll
            for (int x2 = 0; x2 < 8; x2++)
#pragma unroll
                for (int x3 = 0; x3 < 4; x3++) acc[x1][x2][x3] = 0.f;
        gemm128h(sA, sB1, acc, warpRow, warpCol, g, t);

        asm volatile("cp.async.wait_group 0;" ::: "memory");
        __syncthreads();

        // alpha[r] = sum_o leaky(acc + pre[seg[r]][o] + b1[o]) * w2[o] + b2
        float p[2][2];
#pragma unroll
        for (int mt = 0; mt < 2; mt++) { p[mt][0] = 0.f; p[mt][1] = 0.f; }
#pragma unroll
        for (int mt = 0; mt < 2; mt++)
#pragma unroll
            for (int nt = 0; nt < 8; nt++) {
                const int c0 = warpCol * 64 + nt * 8 + 2 * t;
                const int rbase = warpRow * 32 + mt * 16 + g;
#pragma unroll
                for (int j = 0; j < 2; j++) {
                    unsigned pw = sPre[(rbase + j * 8) * LH2 + (c0 >> 1)];
                    float2 pf = __half22float2(*reinterpret_cast<__half2*>(&pw));
                    float x0 = acc[mt][nt][j * 2 + 0] + pf.x + sb1[c0];
                    float x1 = acc[mt][nt][j * 2 + 1] + pf.y + sb1[c0 + 1];
                    x0 = (x0 >= 0.f) ? x0 : SLOPE * x0;
                    x1 = (x1 >= 0.f) ? x1 : SLOPE * x1;
                    p[mt][j] += x0 * sw2[c0] + x1 * sw2[c0 + 1];
                }
            }
#pragma unroll
        for (int mt = 0; mt < 2; mt++)
#pragma unroll
            for (int j = 0; j < 2; j++) {
                float v = p[mt][j];
                v += __shfl_xor_sync(0xffffffffu, v, 1);
                v += __shfl_xor_sync(0xffffffffu, v, 2);
                if ((lane & 3) == 0)
                    sPart[(warpRow * 32 + mt * 16 + g + j * 8) * 2 + warpCol] = v;
            }
        __syncthreads();
        if (tid < rows) {
            float av = sPart[tid * 2] + sPart[tid * 2 + 1] + ba2v;
            g_alpha[(size_t)(row0 + tid) * 4 + h] = av;
            atomicMax(&g_amax[sSeg[tid] * 4 + h], f2key(av));  // fused k_max
        }
        __syncthreads();
    }
}

// ---------------- kernel 2: exp + denom ----------------
__global__ void k_exp(const int* __restrict__ index) {
    int i = blockIdx.x * blockDim.x + threadIdx.x;
    if (i >= N_NODES * HEADS) return;
    int n = i >> 2, h = i & 3;
    int s = index[n] * 4 + h;
    float amax = key2f(g_amax[s]);
    float e = expf(g_alpha[i] - amax);
    g_e[i] = e;
    atomicAdd(&g_denom[s], e);
}

// ---------------- kernel 3: GEMM1 + alpha-weighted segment-sum of hidden ----
// g_H[h][s][:] += alpha_n * leaky(W1.fea_n + b1) for nodes n in segment s.
__global__ void __launch_bounds__(256, 2)
k_msg2(const float* __restrict__ fea,
       const float* __restrict__ Wm1, const float* __restrict__ bm1,
       const int* __restrict__ index) {
    extern __shared__ unsigned smem_u[];
    unsigned* sA  = smem_u;                    // fea tile; later sOut
    unsigned* sB1 = sA + 128 * LH2;
    float* sb1    = (float*)(sB1 + 128 * LH2);
    float* sScale = sb1 + 128;
    int*   sSeg   = (int*)(sScale + 128);
    float* sOut   = (float*)sA;                // [64][LOUT] f32, reuses sA

    const int tid  = threadIdx.x;
    const int lane = tid & 31;
    const int warp = tid >> 5;
    const int warpRow = warp >> 1, warpCol = warp & 1;
    const int g = lane >> 2, t = lane & 3;
    const int h = blockIdx.y;
    float* Hh = g_H + (size_t)h * SEGS * 128;

    load_w_h(sB1, Wm1 + (size_t)h * 128 * 128, 128, tid);
    if (tid < 128) sb1[tid] = bm1[h * 128 + tid];
    __syncthreads();

    for (int tile = blockIdx.x; tile < NTILES; tile += gridDim.x) {
        const int row0 = tile * 128;
        const int rows = min(128, N_NODES - row0);

        if (tid < 128) {
            if (tid < rows) {
                int s = index[row0 + tid];
                sSeg[tid] = s;
                sScale[tid] = g_e[(size_t)(row0 + tid) * 4 + h] /
                              (g_denom[s * 4 + h] + 1e-16f);
            } else {
                sSeg[tid] = index[row0 + rows - 1];
                sScale[tid] = 0.f;
            }
        }
        load_rows_h(sA, fea + (size_t)row0 * 128, rows, tid);
        __syncthreads();

        float acc[2][8][4];
#pragma unroll
        for (int x1 = 0; x1 < 2; x1++)
#pragma unroll
            for (int x2 = 0; x2 < 8; x2++)
#pragma unroll
                for (int x3 = 0; x3 < 4; x3++) acc[x1][x2][x3] = 0.f;
        gemm128h(sA, sB1, acc, warpRow, warpCol, g, t);
        __syncthreads();   // all reads of sA done; reusable as sOut

        // epilogue: alpha * leaky(acc+b1) -> sOut, two 64-row passes,
        // segmented atomic reduce into g_H.
#pragma unroll
        for (int pass = 0; pass < 2; pass++) {
            if ((warpRow >> 1) == pass) {
#pragma unroll
                for (int mt = 0; mt < 2; mt++)
#pragma unroll
                    for (int nt = 0; nt < 8; nt++)
#pragma unroll
                        for (int ip = 0; ip < 2; ip++) {
                            int row  = warpRow * 32 + mt * 16 + g + ip * 8;
                            int lrow = (warpRow & 1) * 32 + mt * 16 + g + ip * 8;
                            int c0 = warpCol * 64 + nt * 8 + 2 * t;
                            float sc = sScale[row];
                            float x0 = acc[mt][nt][ip * 2 + 0] + sb1[c0];
                            float x1 = acc[mt][nt][ip * 2 + 1] + sb1[c0 + 1];
                            x0 = (x0 >= 0.f) ? x0 : SLOPE * x0;
                            x1 = (x1 >= 0.f) ? x1 : SLOPE * x1;
                            float2 v = make_float2(x0 * sc, x1 * sc);
                            *reinterpret_cast<float2*>(sOut + lrow * LOUT + c0) = v;
                        }
            }
            __syncthreads();
            {
                const int c = tid & 127;
                const int lr0 = (tid >> 7) * 32;          // 0 or 32 (local)
                const int gr0 = pass * 64 + lr0;          // global row base
                float accum = 0.f;
                int cur = sSeg[gr0];
                for (int r = 0; r < 32; r++) {
                    int s = sSeg[gr0 + r];
                    if (s != cur) {
                        atomicAdd(&Hh[(size_t)cur * 128 + c], accum);
                        accum = 0.f;
                        cur = s;
                    }
                    accum += sOut[(lr0 + r) * LOUT + c];
                }
                atomicAdd(&Hh[(size_t)cur * 128 + c], accum);
            }
            __syncthreads();
        }
    }
}

// ---------------- kernel 4: out = W2 . H + b2 * indicator ----------------
__global__ void __launch_bounds__(256, 2)
k_out(const float* __restrict__ Wm2, const float* __restrict__ bm2,
      float* __restrict__ out) {
    extern __shared__ unsigned smem_u[];
    unsigned* sA = smem_u;                 // H tile (fp16)
    unsigned* sB = sA + 128 * LH2;         // W2
    float* sb2  = (float*)(sB + 128 * LH2);
    float* sInd = sb2 + 128;

    const int tid  = threadIdx.x;
    const int lane = tid & 31;
    const int warp = tid >> 5;
    const int warpRow = warp >> 1, warpCol = warp & 1;
    const int g = lane >> 2, t = lane & 3;
    const int h  = blockIdx.y;
    const int s0 = blockIdx.x * 128;

    load_w_h(sB, Wm2 + (size_t)h * 128 * 128, 128, tid);
    load_rows_h(sA, g_H + ((size_t)h * SEGS + s0) * 128, 128, tid);
    if (tid < 128) {
        sb2[tid]  = bm2[h * 128 + tid];
        sInd[tid] = (g_denom[(s0 + tid) * 4 + h] > 0.f) ? 1.f : 0.f;
    }
    __syncthreads();

    float acc[2][8][4];
#pragma unroll
    for (int x1 = 0; x1 < 2; x1++)
#pragma unroll
        for (int x2 = 0; x2 < 8; x2++)
#pragma unroll
            for (int x3 = 0; x3 < 4; x3++) acc[x1][x2][x3] = 0.f;
    gemm128h(sA, sB, acc, warpRow, warpCol, g, t);

#pragma unroll
    for (int mt = 0; mt < 2; mt++)
#pragma unroll
        for (int nt = 0; nt < 8; nt++)
#pragma unroll
            for (int ip = 0; ip < 2; ip++) {
                int row = warpRow * 32 + mt * 16 + g + ip * 8;
                int c0 = warpCol * 64 + nt * 8 + 2 * t;
                float a = sInd[row];
                float2 v;
                v.x = acc[mt][nt][ip * 2 + 0] + sb2[c0] * a;
                v.y = acc[mt][nt][ip * 2 + 1] + sb2[c0 + 1] * a;
                *reinterpret_cast<float2*>(
                    out + (size_t)(s0 + row) * 512 + h * 128 + c0) = v;
            }
}

// ---------------- launch ----------------
extern "C" void kernel_launch(void* const* d_in, const int* in_sizes, int n_in,
                              void* d_out, int out_size) {
    (void)in_sizes; (void)n_in; (void)out_size;
    const float* fea = (const float*)d_in[0];
    const float* cry = (const float*)d_in[1];
    const float* Wm1 = (const float*)d_in[2];
    const float* bm1 = (const float*)d_in[3];
    const float* Wm2 = (const float*)d_in[4];
    const float* bm2 = (const float*)d_in[5];
    const float* Wa1 = (const float*)d_in[6];
    const float* ba1 = (const float*)d_in[7];
    const float* Wa2 = (const float*)d_in[8];
    const float* ba2 = (const float*)d_in[9];
    const int*   idx = (const int*)d_in[10];
    float* out = (float*)d_out;

    const size_t smem_pre   = (size_t)(2 * 128 * LH2) * 4;
    const size_t smem_alpha = (size_t)(3 * 128 * LH2 + 128 + 128 + 256 + 128) * 4;
    const size_t smem_msg   = (size_t)(2 * 128 * LH2 + 128 + 128 + 128) * 4;
    const size_t smem_out   = (size_t)(2 * 128 * LH2 + 128 + 128) * 4;
    cudaFuncSetAttribute(k_pre,   cudaFuncAttributeMaxDynamicSharedMemorySize, (int)smem_pre);
    cudaFuncSetAttribute(k_alpha, cudaFuncAttributeMaxDynamicSharedMemorySize, (int)smem_alpha);
    cudaFuncSetAttribute(k_msg2,  cudaFuncAttributeMaxDynamicSharedMemorySize, (int)smem_msg);
    cudaFuncSetAttribute(k_out,   cudaFuncAttributeMaxDynamicSharedMemorySize, (int)smem_out);

    k_init<<<2048, 512>>>();
    k_pre<<<dim3(SEGS / 128, 4), 256, smem_pre>>>(cry, Wa1);
    k_alpha<<<dim3(74, 4), 256, smem_alpha>>>(fea, Wa1, ba1, Wa2, ba2, idx);
    int total = N_NODES * HEADS;
    k_exp<<<(total + 255) / 256, 256>>>(idx);
    k_msg2<<<dim3(74, 4), 256, smem_msg>>>(fea, Wm1, bm1, idx);
    k_out<<<dim3(SEGS / 128, 4), 256, smem_out>>>(Wm2, bm2, out);
}

// round 12
// speedup vs baseline: 1.3704x; 1.0067x over previous
#include <cuda_runtime.h>
#include <cuda_fp16.h>
#include <cstdint>

#define N_NODES 200000
#define SEGS    16384
#define NTILES  ((N_NODES + 127) / 128)   // 1563
#define HEADS   4
#define LH2     68     // smem row stride in half2 units
#define LOUT    132    // f32 out-tile stride
#define SLOPE   0.01f

// ---------------- device scratch ----------------
__device__ float    g_e[N_NODES * HEADS];
__device__ float    g_denom[SEGS * HEADS];
__device__ unsigned g_pre1[HEADS * SEGS * 64];        // fp16x2: W1R . cry per segment
__device__ float    g_H[(size_t)HEADS * SEGS * 128];  // Σ α_n h_n per segment

// ---------------- helpers ----------------
__device__ __forceinline__ unsigned h2pack(float a, float b) {
    unsigned r;
    asm("cvt.rn.f16x2.f32 %0, %2, %1;" : "=r"(r) : "f"(a), "f"(b));
    return r;  // lo = a, hi = b
}

__device__ __forceinline__ void mma_f16(float c[4], const unsigned a[4], const unsigned b[2]) {
    asm volatile(
        "mma.sync.aligned.m16n8k16.row.col.f32.f16.f16.f32 "
        "{%0,%1,%2,%3}, {%4,%5,%6,%7}, {%8,%9}, {%0,%1,%2,%3};\n"
        : "+f"(c[0]), "+f"(c[1]), "+f"(c[2]), "+f"(c[3])
        : "r"(a[0]), "r"(a[1]), "r"(a[2]), "r"(a[3]), "r"(b[0]), "r"(b[1]));
}

__device__ __forceinline__ void cpa16(unsigned saddr, const void* g) {
    asm volatile("cp.async.ca.shared.global [%0], [%1], 16;" :: "r"(saddr), "l"(g) : "memory");
}

// 128x128x128 GEMM: C[r][o] += sum_k A[r][k]*B[o][k]; fp16 half2-packed smem,
// row stride LH2. 8 warps (4x2), warp tile 32x64.
__device__ __forceinline__ void gemm128h(const unsigned* sA, const unsigned* sB,
                                         float (&acc)[2][8][4],
                                         int warpRow, int warpCol, int g, int t) {
#pragma unroll 4
    for (int ks = 0; ks < 8; ks++) {
        const int k0 = ks * 8;
        unsigned a[2][4], b[8][2];
#pragma unroll
        for (int mt = 0; mt < 2; mt++) {
            int r = warpRow * 32 + mt * 16 + g;
            a[mt][0] = sA[r * LH2 + k0 + t];
            a[mt][1] = sA[(r + 8) * LH2 + k0 + t];
            a[mt][2] = sA[r * LH2 + k0 + t + 4];
            a[mt][3] = sA[(r + 8) * LH2 + k0 + t + 4];
        }
#pragma unroll
        for (int nt = 0; nt < 8; nt++) {
            int o = warpCol * 64 + nt * 8 + g;
            b[nt][0] = sB[o * LH2 + k0 + t];
            b[nt][1] = sB[o * LH2 + k0 + t + 4];
        }
#pragma unroll
        for (int mt = 0; mt < 2; mt++)
#pragma unroll
            for (int nt = 0; nt < 8; nt++)
                mma_f16(acc[mt][nt], a[mt], b[nt]);
    }
}

// load [rows<=128,128] f32 -> fp16 smem tile (256 threads)
__device__ __forceinline__ void load_rows_h(unsigned* dst, const float* __restrict__ src,
                                            int rows, int tid) {
#pragma unroll
    for (int i = 0; i < 16; i++) {
        int v = i * 256 + tid;
        int r = v >> 5, c4 = v & 31;
        float4 val = make_float4(0.f, 0.f, 0.f, 0.f);
        if (r < rows) val = reinterpret_cast<const float4*>(src)[r * 32 + c4];
        uint2 u = make_uint2(h2pack(val.x, val.y), h2pack(val.z, val.w));
        *reinterpret_cast<uint2*>(dst + r * LH2 + c4 * 2) = u;
    }
}

__device__ __forceinline__ void load_w_h(unsigned* dst, const float* __restrict__ src,
                                         int srcStride, int tid) {
#pragma unroll
    for (int i = 0; i < 16; i++) {
        int v = i * 256 + tid;
        int r = v >> 5, c4 = v & 31;
        float4 val = *reinterpret_cast<const float4*>(src + (size_t)r * srcStride + c4 * 4);
        uint2 u = make_uint2(h2pack(val.x, val.y), h2pack(val.z, val.w));
        *reinterpret_cast<uint2*>(dst + r * LH2 + c4 * 2) = u;
    }
}

// ---------------- kernel 0: init (zero g_H + denom) ----------------
__global__ void k_init() {
    int i = blockIdx.x * blockDim.x + threadIdx.x;
    int stride = gridDim.x * blockDim.x;
    int n4 = (HEADS * SEGS * 128) >> 2;
    for (int j = i; j < n4; j += stride)
        reinterpret_cast<float4*>(g_H)[j] = make_float4(0.f, 0.f, 0.f, 0.f);
    for (int j = i; j < SEGS * HEADS; j += stride) g_denom[j] = 0.f;
}

// ---------------- kernel pre: pre1[h][s] = W1R . cry[s] (fp16) ----------------
__global__ void __launch_bounds__(256, 1)
k_pre(const float* __restrict__ cry, const float* __restrict__ Wa1) {
    extern __shared__ unsigned smem_u[];
    unsigned* sA = smem_u;              // cry tile
    unsigned* sB = sA + 128 * LH2;      // W1R

    const int tid  = threadIdx.x;
    const int lane = tid & 31;
    const int warp = tid >> 5;
    const int warpRow = warp >> 1, warpCol = warp & 1;
    const int g = lane >> 2, t = lane & 3;
    const int h  = blockIdx.y;
    const int s0 = blockIdx.x * 128;

    load_w_h(sB, Wa1 + (size_t)h * 128 * 256 + 128, 256, tid);
    load_w_h(sA, cry + (size_t)s0 * 128, 128, tid);
    __syncthreads();

    float acc[2][8][4];
#pragma unroll
    for (int x1 = 0; x1 < 2; x1++)
#pragma unroll
        for (int x2 = 0; x2 < 8; x2++)
#pragma unroll
            for (int x3 = 0; x3 < 4; x3++) acc[x1][x2][x3] = 0.f;
    gemm128h(sA, sB, acc, warpRow, warpCol, g, t);

#pragma unroll
    for (int mt = 0; mt < 2; mt++)
#pragma unroll
        for (int nt = 0; nt < 8; nt++)
#pragma unroll
            for (int j = 0; j < 2; j++) {
                int row = warpRow * 32 + mt * 16 + g + j * 8;
                int c0  = warpCol * 64 + nt * 8 + 2 * t;
                g_pre1[((size_t)h * SEGS + s0 + row) * 64 + (c0 >> 1)] =
                    h2pack(acc[mt][nt][j * 2 + 0], acc[mt][nt][j * 2 + 1]);
            }
}

// ---------------- kernel 1: alpha GEMM + fused exp/denom ----------------
// e_n = exp(alpha_n)  (no max subtraction: exact softmax identity; alpha is
// O(1) here so no overflow risk), denom accumulated atomically.
__global__ void __launch_bounds__(256, 2)
k_alpha(const float* __restrict__ fea,
        const float* __restrict__ Wa1, const float* __restrict__ ba1,
        const float* __restrict__ Wa2, const float* __restrict__ ba2,
        const int* __restrict__ index) {
    extern __shared__ unsigned smem_u[];
    unsigned* sA   = smem_u;                  // fea tile
    unsigned* sB1  = sA + 128 * LH2;          // W1L
    unsigned* sPre = sB1 + 128 * LH2;         // gathered pre1 (fp16), stride LH2
    float* sb1   = (float*)(sPre + 128 * LH2);
    float* sw2   = sb1 + 128;
    float* sPart = sw2 + 128;                 // 256
    int*   sSeg  = (int*)(sPart + 256);       // 128

    const int tid  = threadIdx.x;
    const int lane = tid & 31;
    const int warp = tid >> 5;
    const int warpRow = warp >> 1, warpCol = warp & 1;
    const int g = lane >> 2, t = lane & 3;
    const int h = blockIdx.y;

    load_w_h(sB1, Wa1 + (size_t)h * 128 * 256, 256, tid);
    if (tid < 128) {
        sb1[tid] = ba1[h * 128 + tid];
        sw2[tid] = Wa2[h * 128 + tid];
    }
    const float ba2v = ba2[h];
    const unsigned sPreAddr = (unsigned)__cvta_generic_to_shared(sPre);
    const unsigned* preH = g_pre1 + (size_t)h * SEGS * 64;
    __syncthreads();

    for (int tile = blockIdx.x; tile < NTILES; tile += gridDim.x) {
        const int row0 = tile * 128;
        const int rows = min(128, N_NODES - row0);

        if (tid < 128) sSeg[tid] = (tid < rows) ? index[row0 + tid] : 0;
        load_rows_h(sA, fea + (size_t)row0 * 128, rows, tid);
        __syncthreads();

        // gather pre1 rows via cp.async (overlaps GEMM below)
#pragma unroll
        for (int i = 0; i < 8; i++) {
            int v = i * 256 + tid;
            int r = v >> 4, ch = v & 15;
            cpa16(sPreAddr + (unsigned)(r * LH2 + ch * 4) * 4,
                  preH + (size_t)sSeg[r] * 64 + ch * 4);
        }
        asm volatile("cp.async.commit_group;" ::: "memory");

        float acc[2][8][4];
#pragma unroll
        for (int x1 = 0; x1 < 2; x1++)
#pragma unroll
            for (int x2 = 0; x2 < 8; x2++)
#pragma unroll
                for (int x3 = 0; x3 < 4; x3++) acc[x1][x2][x3] = 0.f;
        gemm128h(sA, sB1, acc, warpRow, warpCol, g, t);

        asm volatile("cp.async.wait_group 0;" ::: "memory");
        __syncthreads();

        // alpha[r] = sum_o leaky(acc + pre[seg[r]][o] + b1[o]) * w2[o] + b2
        float p[2][2];
#pragma unroll
        for (int mt = 0; mt < 2; mt++) { p[mt][0] = 0.f; p[mt][1] = 0.f; }
#pragma unroll
        for (int mt = 0; mt < 2; mt++)
#pragma unroll
            for (int nt = 0; nt < 8; nt++) {
                const int c0 = warpCol * 64 + nt * 8 + 2 * t;
                const int rbase = warpRow * 32 + mt * 16 + g;
#pragma unroll
                for (int j = 0; j < 2; j++) {
                    unsigned pw = sPre[(rbase + j * 8) * LH2 + (c0 >> 1)];
                    float2 pf = __half22float2(*reinterpret_cast<__half2*>(&pw));
                    float x0 = acc[mt][nt][j * 2 + 0] + pf.x + sb1[c0];
                    float x1 = acc[mt][nt][j * 2 + 1] + pf.y + sb1[c0 + 1];
                    x0 = (x0 >= 0.f) ? x0 : SLOPE * x0;
                    x1 = (x1 >= 0.f) ? x1 : SLOPE * x1;
                    p[mt][j] += x0 * sw2[c0] + x1 * sw2[c0 + 1];
                }
            }
#pragma unroll
        for (int mt = 0; mt < 2; mt++)
#pragma unroll
            for (int j = 0; j < 2; j++) {
                float v = p[mt][j];
                v += __shfl_xor_sync(0xffffffffu, v, 1);
                v += __shfl_xor_sync(0xffffffffu, v, 2);
                if ((lane & 3) == 0)
                    sPart[(warpRow * 32 + mt * 16 + g + j * 8) * 2 + warpCol] = v;
            }
        __syncthreads();
        if (tid < rows) {
            float av = sPart[tid * 2] + sPart[tid * 2 + 1] + ba2v;
            float e = expf(av);
            g_e[(size_t)(row0 + tid) * 4 + h] = e;
            atomicAdd(&g_denom[sSeg[tid] * 4 + h], e);
        }
        __syncthreads();
    }
}

// ---------------- kernel 2: GEMM1 + alpha-weighted segment-sum of hidden ----
__global__ void __launch_bounds__(256, 2)
k_msg2(const float* __restrict__ fea,
       const float* __restrict__ Wm1, const float* __restrict__ bm1,
       const int* __restrict__ index) {
    extern __shared__ unsigned smem_u[];
    unsigned* sA  = smem_u;                    // fea tile; later sOut
    unsigned* sB1 = sA + 128 * LH2;
    float* sb1    = (float*)(sB1 + 128 * LH2);
    float* sScale = sb1 + 128;
    int*   sSeg   = (int*)(sScale + 128);
    float* sOut   = (float*)sA;                // [64][LOUT] f32, reuses sA

    const int tid  = threadIdx.x;
    const int lane = tid & 31;
    const int warp = tid >> 5;
    const int warpRow = warp >> 1, warpCol = warp & 1;
    const int g = lane >> 2, t = lane & 3;
    const int h = blockIdx.y;
    float* Hh = g_H + (size_t)h * SEGS * 128;

    load_w_h(sB1, Wm1 + (size_t)h * 128 * 128, 128, tid);
    if (tid < 128) sb1[tid] = bm1[h * 128 + tid];
    __syncthreads();

    for (int tile = blockIdx.x; tile < NTILES; tile += gridDim.x) {
        const int row0 = tile * 128;
        const int rows = min(128, N_NODES - row0);

        if (tid < 128) {
            if (tid < rows) {
                int s = index[row0 + tid];
                sSeg[tid] = s;
                sScale[tid] = g_e[(size_t)(row0 + tid) * 4 + h] /
                              (g_denom[s * 4 + h] + 1e-16f);
            } else {
                sSeg[tid] = index[row0 + rows - 1];
                sScale[tid] = 0.f;
            }
        }
        load_rows_h(sA, fea + (size_t)row0 * 128, rows, tid);
        __syncthreads();

        float acc[2][8][4];
#pragma unroll
        for (int x1 = 0; x1 < 2; x1++)
#pragma unroll
            for (int x2 = 0; x2 < 8; x2++)
#pragma unroll
                for (int x3 = 0; x3 < 4; x3++) acc[x1][x2][x3] = 0.f;
        gemm128h(sA, sB1, acc, warpRow, warpCol, g, t);
        __syncthreads();   // all reads of sA done; reusable as sOut

        // epilogue: alpha * leaky(acc+b1) -> sOut, two 64-row passes,
        // segmented atomic reduce into g_H.
#pragma unroll
        for (int pass = 0; pass < 2; pass++) {
            if ((warpRow >> 1) == pass) {
#pragma unroll
                for (int mt = 0; mt < 2; mt++)
#pragma unroll
                    for (int nt = 0; nt < 8; nt++)
#pragma unroll
                        for (int ip = 0; ip < 2; ip++) {
                            int row  = warpRow * 32 + mt * 16 + g + ip * 8;
                            int lrow = (warpRow & 1) * 32 + mt * 16 + g + ip * 8;
                            int c0 = warpCol * 64 + nt * 8 + 2 * t;
                            float sc = sScale[row];
                            float x0 = acc[mt][nt][ip * 2 + 0] + sb1[c0];
                            float x1 = acc[mt][nt][ip * 2 + 1] + sb1[c0 + 1];
                            x0 = (x0 >= 0.f) ? x0 : SLOPE * x0;
                            x1 = (x1 >= 0.f) ? x1 : SLOPE * x1;
                            float2 v = make_float2(x0 * sc, x1 * sc);
                            *reinterpret_cast<float2*>(sOut + lrow * LOUT + c0) = v;
                        }
            }
            __syncthreads();
            {
                const int c = tid & 127;
                const int lr0 = (tid >> 7) * 32;          // 0 or 32 (local)
                const int gr0 = pass * 64 + lr0;          // global row base
                float accum = 0.f;
                int cur = sSeg[gr0];
                for (int r = 0; r < 32; r++) {
                    int s = sSeg[gr0 + r];
                    if (s != cur) {
                        atomicAdd(&Hh[(size_t)cur * 128 + c], accum);
                        accum = 0.f;
                        cur = s;
                    }
                    accum += sOut[(lr0 + r) * LOUT + c];
                }
                atomicAdd(&Hh[(size_t)cur * 128 + c], accum);
            }
            __syncthreads();
        }
    }
}

// ---------------- kernel 3: out = W2 . H + b2 * indicator ----------------
__global__ void __launch_bounds__(256, 2)
k_out(const float* __restrict__ Wm2, const float* __restrict__ bm2,
      float* __restrict__ out) {
    extern __shared__ unsigned smem_u[];
    unsigned* sA = smem_u;                 // H tile (fp16)
    unsigned* sB = sA + 128 * LH2;         // W2
    float* sb2  = (float*)(sB + 128 * LH2);
    float* sInd = sb2 + 128;

    const int tid  = threadIdx.x;
    const int lane = tid & 31;
    const int warp = tid >> 5;
    const int warpRow = warp >> 1, warpCol = warp & 1;
    const int g = lane >> 2, t = lane & 3;
    const int h  = blockIdx.y;
    const int s0 = blockIdx.x * 128;

    load_w_h(sB, Wm2 + (size_t)h * 128 * 128, 128, tid);
    load_rows_h(sA, g_H + ((size_t)h * SEGS + s0) * 128, 128, tid);
    if (tid < 128) {
        sb2[tid]  = bm2[h * 128 + tid];
        sInd[tid] = (g_denom[(s0 + tid) * 4 + h] > 0.f) ? 1.f : 0.f;
    }
    __syncthreads();

    float acc[2][8][4];
#pragma unroll
    for (int x1 = 0; x1 < 2; x1++)
#pragma unroll
        for (int x2 = 0; x2 < 8; x2++)
#pragma unroll
            for (int x3 = 0; x3 < 4; x3++) acc[x1][x2][x3] = 0.f;
    gemm128h(sA, sB, acc, warpRow, warpCol, g, t);

#pragma unroll
    for (int mt = 0; mt < 2; mt++)
#pragma unroll
        for (int nt = 0; nt < 8; nt++)
#pragma unroll
            for (int ip = 0; ip < 2; ip++) {
                int row = warpRow * 32 + mt * 16 + g + ip * 8;
                int c0 = warpCol * 64 + nt * 8 + 2 * t;
                float a = sInd[row];
                float2 v;
                v.x = acc[mt][nt][ip * 2 + 0] + sb2[c0] * a;
                v.y = acc[mt][nt][ip * 2 + 1] + sb2[c0 + 1] * a;
                *reinterpret_cast<float2*>(
                    out + (size_t)(s0 + row) * 512 + h * 128 + c0) = v;
            }
}

// ---------------- launch ----------------
extern "C" void kernel_launch(void* const* d_in, const int* in_sizes, int n_in,
                              void* d_out, int out_size) {
    (void)in_sizes; (void)n_in; (void)out_size;
    const float* fea = (const float*)d_in[0];
    const float* cry = (const float*)d_in[1];
    const float* Wm1 = (const float*)d_in[2];
    const float* bm1 = (const float*)d_in[3];
    const float* Wm2 = (const float*)d_in[4];
    const float* bm2 = (const float*)d_in[5];
    const float* Wa1 = (const float*)d_in[6];
    const float* ba1 = (const float*)d_in[7];
    const float* Wa2 = (const float*)d_in[8];
    const float* ba2 = (const float*)d_in[9];
    const int*   idx = (const int*)d_in[10];
    float* out = (float*)d_out;

    const size_t smem_pre   = (size_t)(2 * 128 * LH2) * 4;
    const size_t smem_alpha = (size_t)(3 * 128 * LH2 + 128 + 128 + 256 + 128) * 4;
    const size_t smem_msg   = (size_t)(2 * 128 * LH2 + 128 + 128 + 128) * 4;
    const size_t smem_out   = (size_t)(2 * 128 * LH2 + 128 + 128) * 4;
    cudaFuncSetAttribute(k_pre,   cudaFuncAttributeMaxDynamicSharedMemorySize, (int)smem_pre);
    cudaFuncSetAttribute(k_alpha, cudaFuncAttributeMaxDynamicSharedMemorySize, (int)smem_alpha);
    cudaFuncSetAttribute(k_msg2,  cudaFuncAttributeMaxDynamicSharedMemorySize, (int)smem_msg);
    cudaFuncSetAttribute(k_out,   cudaFuncAttributeMaxDynamicSharedMemorySize, (int)smem_out);

    k_init<<<2048, 512>>>();
    k_pre<<<dim3(SEGS / 128, 4), 256, smem_pre>>>(cry, Wa1);
    k_alpha<<<dim3(74, 4), 256, smem_alpha>>>(fea, Wa1, ba1, Wa2, ba2, idx);
    k_msg2<<<dim3(74, 4), 256, smem_msg>>>(fea, Wm1, bm1, idx);
    k_out<<<dim3(SEGS / 128, 4), 256, smem_out>>>(Wm2, bm2, out);
}

// round 13
// speedup vs baseline: 1.4031x; 1.0239x over previous
#include <cuda_runtime.h>
#include <cuda_fp16.h>
#include <cstdint>

#define N_NODES 200000
#define SEGS    16384
#define NTILES  ((N_NODES + 127) / 128)   // 1563
#define HEADS   4
#define LH2     68     // smem row stride in half2 units (272 B)
#define LOUT    132    // f32 out-tile stride
#define SLOPE   0.01f

// ---------------- device scratch ----------------
__device__ float    g_e[N_NODES * HEADS];
__device__ float    g_denom[SEGS * HEADS];
__device__ unsigned g_pre1[HEADS * SEGS * 64];        // fp16x2: W1R . cry per segment
__device__ float    g_H[(size_t)HEADS * SEGS * 128];  // Σ α_n h_n per segment

// ---------------- helpers ----------------
__device__ __forceinline__ unsigned h2pack(float a, float b) {
    unsigned r;
    asm("cvt.rn.f16x2.f32 %0, %2, %1;" : "=r"(r) : "f"(a), "f"(b));
    return r;  // lo = a, hi = b
}

__device__ __forceinline__ void mma_f16(float c[4], const unsigned a[4], const unsigned b[2]) {
    asm volatile(
        "mma.sync.aligned.m16n8k16.row.col.f32.f16.f16.f32 "
        "{%0,%1,%2,%3}, {%4,%5,%6,%7}, {%8,%9}, {%0,%1,%2,%3};\n"
        : "+f"(c[0]), "+f"(c[1]), "+f"(c[2]), "+f"(c[3])
        : "r"(a[0]), "r"(a[1]), "r"(a[2]), "r"(a[3]), "r"(b[0]), "r"(b[1]));
}

__device__ __forceinline__ void ldsm_x4(unsigned &r0, unsigned &r1, unsigned &r2, unsigned &r3,
                                        unsigned addr) {
    asm volatile("ldmatrix.sync.aligned.m8n8.x4.shared.b16 {%0,%1,%2,%3}, [%4];"
                 : "=r"(r0), "=r"(r1), "=r"(r2), "=r"(r3) : "r"(addr));
}

__device__ __forceinline__ void cpa16(unsigned saddr, const void* g) {
    asm volatile("cp.async.ca.shared.global [%0], [%1], 16;" :: "r"(saddr), "l"(g) : "memory");
}

// 128x128x128 GEMM: C[r][o] += sum_k A[r][k]*B[o][k]; fp16 half2-packed smem,
// row stride 272B. 8 warps (4x2), warp tile 32x64. Fragments via ldmatrix.x4.
__device__ __forceinline__ void gemm128h(const unsigned* sA, const unsigned* sB,
                                         float (&acc)[2][8][4],
                                         int warpRow, int warpCol, int lane) {
    const unsigned sAb = (unsigned)__cvta_generic_to_shared(sA);
    const unsigned sBb = (unsigned)__cvta_generic_to_shared(sB);
    const int l15 = lane & 15, l7 = lane & 7;
    unsigned aAddr[2], bAddr[4];
#pragma unroll
    for (int mt = 0; mt < 2; mt++)
        aAddr[mt] = sAb + (unsigned)((warpRow * 32 + mt * 16 + l15) * 272 + (lane >> 4) * 16);
#pragma unroll
    for (int p = 0; p < 4; p++)
        bAddr[p] = sBb + (unsigned)((warpCol * 64 + p * 16 + l7 + ((lane & 16) >> 1)) * 272
                                    + ((lane >> 3) & 1) * 16);
#pragma unroll
    for (int ks = 0; ks < 8; ks++) {
        unsigned a[2][4], b[8][2];
#pragma unroll
        for (int mt = 0; mt < 2; mt++) {
            ldsm_x4(a[mt][0], a[mt][1], a[mt][2], a[mt][3], aAddr[mt]);
            aAddr[mt] += 32;
        }
#pragma unroll
        for (int p = 0; p < 4; p++) {
            ldsm_x4(b[2 * p][0], b[2 * p][1], b[2 * p + 1][0], b[2 * p + 1][1], bAddr[p]);
            bAddr[p] += 32;
        }
#pragma unroll
        for (int mt = 0; mt < 2; mt++)
#pragma unroll
            for (int nt = 0; nt < 8; nt++)
                mma_f16(acc[mt][nt], a[mt], b[nt]);
    }
}

// load [rows<=128,128] f32 -> fp16 smem tile (256 threads)
__device__ __forceinline__ void load_rows_h(unsigned* dst, const float* __restrict__ src,
                                            int rows, int tid) {
#pragma unroll
    for (int i = 0; i < 16; i++) {
        int v = i * 256 + tid;
        int r = v >> 5, c4 = v & 31;
        float4 val = make_float4(0.f, 0.f, 0.f, 0.f);
        if (r < rows) val = reinterpret_cast<const float4*>(src)[r * 32 + c4];
        uint2 u = make_uint2(h2pack(val.x, val.y), h2pack(val.z, val.w));
        *reinterpret_cast<uint2*>(dst + r * LH2 + c4 * 2) = u;
    }
}

__device__ __forceinline__ void load_w_h(unsigned* dst, const float* __restrict__ src,
                                         int srcStride, int tid) {
#pragma unroll
    for (int i = 0; i < 16; i++) {
        int v = i * 256 + tid;
        int r = v >> 5, c4 = v & 31;
        float4 val = *reinterpret_cast<const float4*>(src + (size_t)r * srcStride + c4 * 4);
        uint2 u = make_uint2(h2pack(val.x, val.y), h2pack(val.z, val.w));
        *reinterpret_cast<uint2*>(dst + r * LH2 + c4 * 2) = u;
    }
}

// ---------------- kernel 0: init (zero g_H + denom) ----------------
__global__ void k_init() {
    int i = blockIdx.x * blockDim.x + threadIdx.x;
    int stride = gridDim.x * blockDim.x;
    int n4 = (HEADS * SEGS * 128) >> 2;
    for (int j = i; j < n4; j += stride)
        reinterpret_cast<float4*>(g_H)[j] = make_float4(0.f, 0.f, 0.f, 0.f);
    for (int j = i; j < SEGS * HEADS; j += stride) g_denom[j] = 0.f;
}

// ---------------- kernel pre: pre1[h][s] = W1R . cry[s] (fp16) ----------------
__global__ void __launch_bounds__(256, 1)
k_pre(const float* __restrict__ cry, const float* __restrict__ Wa1) {
    extern __shared__ unsigned smem_u[];
    unsigned* sA = smem_u;              // cry tile
    unsigned* sB = sA + 128 * LH2;      // W1R

    const int tid  = threadIdx.x;
    const int lane = tid & 31;
    const int warp = tid >> 5;
    const int warpRow = warp >> 1, warpCol = warp & 1;
    const int g = lane >> 2, t = lane & 3;
    const int h  = blockIdx.y;
    const int s0 = blockIdx.x * 128;

    load_w_h(sB, Wa1 + (size_t)h * 128 * 256 + 128, 256, tid);
    load_w_h(sA, cry + (size_t)s0 * 128, 128, tid);
    __syncthreads();

    float acc[2][8][4];
#pragma unroll
    for (int x1 = 0; x1 < 2; x1++)
#pragma unroll
        for (int x2 = 0; x2 < 8; x2++)
#pragma unroll
            for (int x3 = 0; x3 < 4; x3++) acc[x1][x2][x3] = 0.f;
    gemm128h(sA, sB, acc, warpRow, warpCol, lane);

#pragma unroll
    for (int mt = 0; mt < 2; mt++)
#pragma unroll
        for (int nt = 0; nt < 8; nt++)
#pragma unroll
            for (int j = 0; j < 2; j++) {
                int row = warpRow * 32 + mt * 16 + g + j * 8;
                int c0  = warpCol * 64 + nt * 8 + 2 * t;
                g_pre1[((size_t)h * SEGS + s0 + row) * 64 + (c0 >> 1)] =
                    h2pack(acc[mt][nt][j * 2 + 0], acc[mt][nt][j * 2 + 1]);
            }
}

// ---------------- kernel 1: alpha GEMM + fused exp/denom ----------------
__global__ void __launch_bounds__(256, 2)
k_alpha(const float* __restrict__ fea,
        const float* __restrict__ Wa1, const float* __restrict__ ba1,
        const float* __restrict__ Wa2, const float* __restrict__ ba2,
        const int* __restrict__ index) {
    extern __shared__ unsigned smem_u[];
    unsigned* sA   = smem_u;                  // fea tile
    unsigned* sB1  = sA + 128 * LH2;          // W1L
    unsigned* sPre = sB1 + 128 * LH2;         // gathered pre1 (fp16), stride LH2
    float* sb1   = (float*)(sPre + 128 * LH2);
    float* sw2   = sb1 + 128;
    float* sPart = sw2 + 128;                 // 256
    int*   sSeg  = (int*)(sPart + 256);       // 128

    const int tid  = threadIdx.x;
    const int lane = tid & 31;
    const int warp = tid >> 5;
    const int warpRow = warp >> 1, warpCol = warp & 1;
    const int g = lane >> 2, t = lane & 3;
    const int h = blockIdx.y;

    load_w_h(sB1, Wa1 + (size_t)h * 128 * 256, 256, tid);
    if (tid < 128) {
        sb1[tid] = ba1[h * 128 + tid];
        sw2[tid] = Wa2[h * 128 + tid];
    }
    const float ba2v = ba2[h];
    const unsigned sPreAddr = (unsigned)__cvta_generic_to_shared(sPre);
    const unsigned* preH = g_pre1 + (size_t)h * SEGS * 64;
    __syncthreads();

    for (int tile = blockIdx.x; tile < NTILES; tile += gridDim.x) {
        const int row0 = tile * 128;
        const int rows = min(128, N_NODES - row0);

        if (tid < 128) sSeg[tid] = (tid < rows) ? index[row0 + tid] : 0;
        load_rows_h(sA, fea + (size_t)row0 * 128, rows, tid);
        __syncthreads();

        // gather pre1 rows via cp.async (overlaps GEMM below)
#pragma unroll
        for (int i = 0; i < 8; i++) {
            int v = i * 256 + tid;
            int r = v >> 4, ch = v & 15;
            cpa16(sPreAddr + (unsigned)(r * LH2 + ch * 4) * 4,
                  preH + (size_t)sSeg[r] * 64 + ch * 4);
        }
        asm volatile("cp.async.commit_group;" ::: "memory");

        float acc[2][8][4];
#pragma unroll
        for (int x1 = 0; x1 < 2; x1++)
#pragma unroll
            for (int x2 = 0; x2 < 8; x2++)
#pragma unroll
                for (int x3 = 0; x3 < 4; x3++) acc[x1][x2][x3] = 0.f;
        gemm128h(sA, sB1, acc, warpRow, warpCol, lane);

        asm volatile("cp.async.wait_group 0;" ::: "memory");
        __syncthreads();

        // alpha[r] = sum_o leaky(acc + pre[seg[r]][o] + b1[o]) * w2[o] + b2
        float p[2][2];
#pragma unroll
        for (int mt = 0; mt < 2; mt++) { p[mt][0] = 0.f; p[mt][1] = 0.f; }
#pragma unroll
        for (int mt = 0; mt < 2; mt++)
#pragma unroll
            for (int nt = 0; nt < 8; nt++) {
                const int c0 = warpCol * 64 + nt * 8 + 2 * t;
                const int rbase = warpRow * 32 + mt * 16 + g;
#pragma unroll
                for (int j = 0; j < 2; j++) {
                    unsigned pw = sPre[(rbase + j * 8) * LH2 + (c0 >> 1)];
                    float2 pf = __half22float2(*reinterpret_cast<__half2*>(&pw));
                    float x0 = acc[mt][nt][j * 2 + 0] + pf.x + sb1[c0];
                    float x1 = acc[mt][nt][j * 2 + 1] + pf.y + sb1[c0 + 1];
                    x0 = (x0 >= 0.f) ? x0 : SLOPE * x0;
                    x1 = (x1 >= 0.f) ? x1 : SLOPE * x1;
                    p[mt][j] += x0 * sw2[c0] + x1 * sw2[c0 + 1];
                }
            }
#pragma unroll
        for (int mt = 0; mt < 2; mt++)
#pragma unroll
            for (int j = 0; j < 2; j++) {
                float v = p[mt][j];
                v += __shfl_xor_sync(0xffffffffu, v, 1);
                v += __shfl_xor_sync(0xffffffffu, v, 2);
                if ((lane & 3) == 0)
                    sPart[(warpRow * 32 + mt * 16 + g + j * 8) * 2 + warpCol] = v;
            }
        __syncthreads();
        if (tid < rows) {
            float av = sPart[tid * 2] + sPart[tid * 2 + 1] + ba2v;
            float e = expf(av);
            g_e[(size_t)(row0 + tid) * 4 + h] = e;
            atomicAdd(&g_denom[sSeg[tid] * 4 + h], e);
        }
        __syncthreads();
    }
}

// ---------------- kernel 2: GEMM1 + alpha-weighted segment-sum of hidden ----
__global__ void __launch_bounds__(256, 2)
k_msg2(const float* __restrict__ fea,
       const float* __restrict__ Wm1, const float* __restrict__ bm1,
       const int* __restrict__ index) {
    extern __shared__ unsigned smem_u[];
    unsigned* sA  = smem_u;                    // fea tile; later sOut
    unsigned* sB1 = sA + 128 * LH2;
    float* sb1    = (float*)(sB1 + 128 * LH2);
    float* sScale = sb1 + 128;
    int*   sSeg   = (int*)(sScale + 128);
    float* sOut   = (float*)sA;                // [64][LOUT] f32, reuses sA

    const int tid  = threadIdx.x;
    const int lane = tid & 31;
    const int warp = tid >> 5;
    const int warpRow = warp >> 1, warpCol = warp & 1;
    const int g = lane >> 2, t = lane & 3;
    const int h = blockIdx.y;
    float* Hh = g_H + (size_t)h * SEGS * 128;

    load_w_h(sB1, Wm1 + (size_t)h * 128 * 128, 128, tid);
    if (tid < 128) sb1[tid] = bm1[h * 128 + tid];
    __syncthreads();

    for (int tile = blockIdx.x; tile < NTILES; tile += gridDim.x) {
        const int row0 = tile * 128;
        const int rows = min(128, N_NODES - row0);

        if (tid < 128) {
            if (tid < rows) {
                int s = index[row0 + tid];
                sSeg[tid] = s;
                sScale[tid] = g_e[(size_t)(row0 + tid) * 4 + h] /
                              (g_denom[s * 4 + h] + 1e-16f);
            } else {
                sSeg[tid] = index[row0 + rows - 1];
                sScale[tid] = 0.f;
            }
        }
        load_rows_h(sA, fea + (size_t)row0 * 128, rows, tid);
        __syncthreads();

        float acc[2][8][4];
#pragma unroll
        for (int x1 = 0; x1 < 2; x1++)
#pragma unroll
            for (int x2 = 0; x2 < 8; x2++)
#pragma unroll
                for (int x3 = 0; x3 < 4; x3++) acc[x1][x2][x3] = 0.f;
        gemm128h(sA, sB1, acc, warpRow, warpCol, lane);
        __syncthreads();   // all reads of sA done; reusable as sOut

        // epilogue: alpha * leaky(acc+b1) -> sOut, two 64-row passes,
        // segmented atomic reduce into g_H.
#pragma unroll
        for (int pass = 0; pass < 2; pass++) {
            if ((warpRow >> 1) == pass) {
#pragma unroll
                for (int mt = 0; mt < 2; mt++)
#pragma unroll
                    for (int nt = 0; nt < 8; nt++)
#pragma unroll
                        for (int ip = 0; ip < 2; ip++) {
                            int row  = warpRow * 32 + mt * 16 + g + ip * 8;
                            int lrow = (warpRow & 1) * 32 + mt * 16 + g + ip * 8;
                            int c0 = warpCol * 64 + nt * 8 + 2 * t;
                            float sc = sScale[row];
                            float x0 = acc[mt][nt][ip * 2 + 0] + sb1[c0];
                            float x1 = acc[mt][nt][ip * 2 + 1] + sb1[c0 + 1];
                            x0 = (x0 >= 0.f) ? x0 : SLOPE * x0;
                            x1 = (x1 >= 0.f) ? x1 : SLOPE * x1;
                            float2 v = make_float2(x0 * sc, x1 * sc);
                            *reinterpret_cast<float2*>(sOut + lrow * LOUT + c0) = v;
                        }
            }
            __syncthreads();
            {
                const int c = tid & 127;
                const int lr0 = (tid >> 7) * 32;          // 0 or 32 (local)
                const int gr0 = pass * 64 + lr0;          // global row base
                float accum = 0.f;
                int cur = sSeg[gr0];
                for (int r = 0; r < 32; r++) {
                    int s = sSeg[gr0 + r];
                    if (s != cur) {
                        atomicAdd(&Hh[(size_t)cur * 128 + c], accum);
                        accum = 0.f;
                        cur = s;
                    }
                    accum += sOut[(lr0 + r) * LOUT + c];
                }
                atomicAdd(&Hh[(size_t)cur * 128 + c], accum);
            }
            __syncthreads();
        }
    }
}

// ---------------- kernel 3: out = W2 . H + b2 * indicator ----------------
__global__ void __launch_bounds__(256, 2)
k_out(const float* __restrict__ Wm2, const float* __restrict__ bm2,
      float* __restrict__ out) {
    extern __shared__ unsigned smem_u[];
    unsigned* sA = smem_u;                 // H tile (fp16)
    unsigned* sB = sA + 128 * LH2;         // W2
    float* sb2  = (float*)(sB + 128 * LH2);
    float* sInd = sb2 + 128;

    const int tid  = threadIdx.x;
    const int lane = tid & 31;
    const int warp = tid >> 5;
    const int warpRow = warp >> 1, warpCol = warp & 1;
    const int g = lane >> 2, t = lane & 3;
    const int h  = blockIdx.y;
    const int s0 = blockIdx.x * 128;

    load_w_h(sB, Wm2 + (size_t)h * 128 * 128, 128, tid);
    load_rows_h(sA, g_H + ((size_t)h * SEGS + s0) * 128, 128, tid);
    if (tid < 128) {
        sb2[tid]  = bm2[h * 128 + tid];
        sInd[tid] = (g_denom[(s0 + tid) * 4 + h] > 0.f) ? 1.f : 0.f;
    }
    __syncthreads();

    float acc[2][8][4];
#pragma unroll
    for (int x1 = 0; x1 < 2; x1++)
#pragma unroll
        for (int x2 = 0; x2 < 8; x2++)
#pragma unroll
            for (int x3 = 0; x3 < 4; x3++) acc[x1][x2][x3] = 0.f;
    gemm128h(sA, sB, acc, warpRow, warpCol, lane);

#pragma unroll
    for (int mt = 0; mt < 2; mt++)
#pragma unroll
        for (int nt = 0; nt < 8; nt++)
#pragma unroll
            for (int ip = 0; ip < 2; ip++) {
                int row = warpRow * 32 + mt * 16 + g + ip * 8;
                int c0 = warpCol * 64 + nt * 8 + 2 * t;
                float a = sInd[row];
                float2 v;
                v.x = acc[mt][nt][ip * 2 + 0] + sb2[c0] * a;
                v.y = acc[mt][nt][ip * 2 + 1] + sb2[c0 + 1] * a;
                *reinterpret_cast<float2*>(
                    out + (size_t)(s0 + row) * 512 + h * 128 + c0) = v;
            }
}

// ---------------- launch ----------------
extern "C" void kernel_launch(void* const* d_in, const int* in_sizes, int n_in,
                              void* d_out, int out_size) {
    (void)in_sizes; (void)n_in; (void)out_size;
    const float* fea = (const float*)d_in[0];
    const float* cry = (const float*)d_in[1];
    const float* Wm1 = (const float*)d_in[2];
    const float* bm1 = (const float*)d_in[3];
    const float* Wm2 = (const float*)d_in[4];
    const float* bm2 = (const float*)d_in[5];
    const float* Wa1 = (const float*)d_in[6];
    const float* ba1 = (const float*)d_in[7];
    const float* Wa2 = (const float*)d_in[8];
    const float* ba2 = (const float*)d_in[9];
    const int*   idx = (const int*)d_in[10];
    float* out = (float*)d_out;

    const size_t smem_pre   = (size_t)(2 * 128 * LH2) * 4;
    const size_t smem_alpha = (size_t)(3 * 128 * LH2 + 128 + 128 + 256 + 128) * 4;
    const size_t smem_msg   = (size_t)(2 * 128 * LH2 + 128 + 128 + 128) * 4;
    const size_t smem_out   = (size_t)(2 * 128 * LH2 + 128 + 128) * 4;
    cudaFuncSetAttribute(k_pre,   cudaFuncAttributeMaxDynamicSharedMemorySize, (int)smem_pre);
    cudaFuncSetAttribute(k_alpha, cudaFuncAttributeMaxDynamicSharedMemorySize, (int)smem_alpha);
    cudaFuncSetAttribute(k_msg2,  cudaFuncAttributeMaxDynamicSharedMemorySize, (int)smem_msg);
    cudaFuncSetAttribute(k_out,   cudaFuncAttributeMaxDynamicSharedMemorySize, (int)smem_out);

    k_init<<<2048, 512>>>();
    k_pre<<<dim3(SEGS / 128, 4), 256, smem_pre>>>(cry, Wa1);
    k_alpha<<<dim3(74, 4), 256, smem_alpha>>>(fea, Wa1, ba1, Wa2, ba2, idx);
    k_msg2<<<dim3(74, 4), 256, smem_msg>>>(fea, Wm1, bm1, idx);
    k_out<<<dim3(SEGS / 128, 4), 256, smem_out>>>(Wm2, bm2, out);
}

// round 14
// speedup vs baseline: 1.4815x; 1.0558x over previous
#include <cuda_runtime.h>
#include <cuda_fp16.h>
#include <cstdint>

#define N_NODES 200000
#define SEGS    16384
#define NTILES  ((N_NODES + 127) / 128)   // 1563
#define HEADS   4
#define LH2     68     // smem row stride in half2 units (272 B)
#define SLOPE   0.01f

// ---------------- device scratch ----------------
__device__ float    g_e[N_NODES * HEADS];
__device__ float    g_denom[SEGS * HEADS];
__device__ unsigned g_pre1[HEADS * SEGS * 64];        // fp16x2: W1R . cry per segment
__device__ float    g_H[(size_t)HEADS * SEGS * 128];  // Σ α_n h_n per segment

// ---------------- helpers ----------------
__device__ __forceinline__ unsigned h2pack(float a, float b) {
    unsigned r;
    asm("cvt.rn.f16x2.f32 %0, %2, %1;" : "=r"(r) : "f"(a), "f"(b));
    return r;  // lo = a, hi = b
}

__device__ __forceinline__ void mma_f16(float c[4], const unsigned a[4], const unsigned b[2]) {
    asm volatile(
        "mma.sync.aligned.m16n8k16.row.col.f32.f16.f16.f32 "
        "{%0,%1,%2,%3}, {%4,%5,%6,%7}, {%8,%9}, {%0,%1,%2,%3};\n"
        : "+f"(c[0]), "+f"(c[1]), "+f"(c[2]), "+f"(c[3])
        : "r"(a[0]), "r"(a[1]), "r"(a[2]), "r"(a[3]), "r"(b[0]), "r"(b[1]));
}

__device__ __forceinline__ void ldsm_x4(unsigned &r0, unsigned &r1, unsigned &r2, unsigned &r3,
                                        unsigned addr) {
    asm volatile("ldmatrix.sync.aligned.m8n8.x4.shared.b16 {%0,%1,%2,%3}, [%4];"
                 : "=r"(r0), "=r"(r1), "=r"(r2), "=r"(r3) : "r"(addr));
}

__device__ __forceinline__ void cpa16(unsigned saddr, const void* g) {
    asm volatile("cp.async.ca.shared.global [%0], [%1], 16;" :: "r"(saddr), "l"(g) : "memory");
}

// 128x128x128 GEMM: C[r][o] += sum_k A[r][k]*B[o][k]; fp16 half2-packed smem,
// row stride 272B. 8 warps (4x2), warp tile 32x64. Fragments via ldmatrix.x4.
__device__ __forceinline__ void gemm128h(const unsigned* sA, const unsigned* sB,
                                         float (&acc)[2][8][4],
                                         int warpRow, int warpCol, int lane) {
    const unsigned sAb = (unsigned)__cvta_generic_to_shared(sA);
    const unsigned sBb = (unsigned)__cvta_generic_to_shared(sB);
    const int l15 = lane & 15, l7 = lane & 7;
    unsigned aAddr[2], bAddr[4];
#pragma unroll
    for (int mt = 0; mt < 2; mt++)
        aAddr[mt] = sAb + (unsigned)((warpRow * 32 + mt * 16 + l15) * 272 + (lane >> 4) * 16);
#pragma unroll
    for (int p = 0; p < 4; p++)
        bAddr[p] = sBb + (unsigned)((warpCol * 64 + p * 16 + l7 + ((lane & 16) >> 1)) * 272
                                    + ((lane >> 3) & 1) * 16);
#pragma unroll
    for (int ks = 0; ks < 8; ks++) {
        unsigned a[2][4], b[8][2];
#pragma unroll
        for (int mt = 0; mt < 2; mt++) {
            ldsm_x4(a[mt][0], a[mt][1], a[mt][2], a[mt][3], aAddr[mt]);
            aAddr[mt] += 32;
        }
#pragma unroll
        for (int p = 0; p < 4; p++) {
            ldsm_x4(b[2 * p][0], b[2 * p][1], b[2 * p + 1][0], b[2 * p + 1][1], bAddr[p]);
            bAddr[p] += 32;
        }
#pragma unroll
        for (int mt = 0; mt < 2; mt++)
#pragma unroll
            for (int nt = 0; nt < 8; nt++)
                mma_f16(acc[mt][nt], a[mt], b[nt]);
    }
}

// load [rows<=128,128] f32 -> fp16 smem tile (256 threads)
__device__ __forceinline__ void load_rows_h(unsigned* dst, const float* __restrict__ src,
                                            int rows, int tid) {
#pragma unroll
    for (int i = 0; i < 16; i++) {
        int v = i * 256 + tid;
        int r = v >> 5, c4 = v & 31;
        float4 val = make_float4(0.f, 0.f, 0.f, 0.f);
        if (r < rows) val = reinterpret_cast<const float4*>(src)[r * 32 + c4];
        uint2 u = make_uint2(h2pack(val.x, val.y), h2pack(val.z, val.w));
        *reinterpret_cast<uint2*>(dst + r * LH2 + c4 * 2) = u;
    }
}

__device__ __forceinline__ void load_w_h(unsigned* dst, const float* __restrict__ src,
                                         int srcStride, int tid) {
#pragma unroll
    for (int i = 0; i < 16; i++) {
        int v = i * 256 + tid;
        int r = v >> 5, c4 = v & 31;
        float4 val = *reinterpret_cast<const float4*>(src + (size_t)r * srcStride + c4 * 4);
        uint2 u = make_uint2(h2pack(val.x, val.y), h2pack(val.z, val.w));
        *reinterpret_cast<uint2*>(dst + r * LH2 + c4 * 2) = u;
    }
}

// ---------------- kernel 0: init (zero g_H + denom) ----------------
__global__ void k_init() {
    int i = blockIdx.x * blockDim.x + threadIdx.x;
    int stride = gridDim.x * blockDim.x;
    int n4 = (HEADS * SEGS * 128) >> 2;
    for (int j = i; j < n4; j += stride)
        reinterpret_cast<float4*>(g_H)[j] = make_float4(0.f, 0.f, 0.f, 0.f);
    for (int j = i; j < SEGS * HEADS; j += stride) g_denom[j] = 0.f;
}

// ---------------- kernel pre: pre1[h][s] = W1R . cry[s] (fp16) ----------------
__global__ void __launch_bounds__(256, 1)
k_pre(const float* __restrict__ cry, const float* __restrict__ Wa1) {
    extern __shared__ unsigned smem_u[];
    unsigned* sA = smem_u;              // cry tile
    unsigned* sB = sA + 128 * LH2;      // W1R

    const int tid  = threadIdx.x;
    const int lane = tid & 31;
    const int warp = tid >> 5;
    const int warpRow = warp >> 1, warpCol = warp & 1;
    const int g = lane >> 2, t = lane & 3;
    const int h  = blockIdx.y;
    const int s0 = blockIdx.x * 128;

    load_w_h(sB, Wa1 + (size_t)h * 128 * 256 + 128, 256, tid);
    load_w_h(sA, cry + (size_t)s0 * 128, 128, tid);
    __syncthreads();

    float acc[2][8][4];
#pragma unroll
    for (int x1 = 0; x1 < 2; x1++)
#pragma unroll
        for (int x2 = 0; x2 < 8; x2++)
#pragma unroll
            for (int x3 = 0; x3 < 4; x3++) acc[x1][x2][x3] = 0.f;
    gemm128h(sA, sB, acc, warpRow, warpCol, lane);

#pragma unroll
    for (int mt = 0; mt < 2; mt++)
#pragma unroll
        for (int nt = 0; nt < 8; nt++)
#pragma unroll
            for (int j = 0; j < 2; j++) {
                int row = warpRow * 32 + mt * 16 + g + j * 8;
                int c0  = warpCol * 64 + nt * 8 + 2 * t;
                g_pre1[((size_t)h * SEGS + s0 + row) * 64 + (c0 >> 1)] =
                    h2pack(acc[mt][nt][j * 2 + 0], acc[mt][nt][j * 2 + 1]);
            }
}

// ---------------- kernel 1: alpha GEMM + fused exp/denom ----------------
__global__ void __launch_bounds__(256, 2)
k_alpha(const float* __restrict__ fea,
        const float* __restrict__ Wa1, const float* __restrict__ ba1,
        const float* __restrict__ Wa2, const float* __restrict__ ba2,
        const int* __restrict__ index) {
    extern __shared__ unsigned smem_u[];
    unsigned* sA   = smem_u;                  // fea tile
    unsigned* sB1  = sA + 128 * LH2;          // W1L
    unsigned* sPre = sB1 + 128 * LH2;         // gathered pre1 (fp16), stride LH2
    float* sb1   = (float*)(sPre + 128 * LH2);
    float* sw2   = sb1 + 128;
    float* sPart = sw2 + 128;                 // 256
    int*   sSeg  = (int*)(sPart + 256);       // 128

    const int tid  = threadIdx.x;
    const int lane = tid & 31;
    const int warp = tid >> 5;
    const int warpRow = warp >> 1, warpCol = warp & 1;
    const int g = lane >> 2, t = lane & 3;
    const int h = blockIdx.y;

    load_w_h(sB1, Wa1 + (size_t)h * 128 * 256, 256, tid);
    if (tid < 128) {
        sb1[tid] = ba1[h * 128 + tid];
        sw2[tid] = Wa2[h * 128 + tid];
    }
    const float ba2v = ba2[h];
    const unsigned sPreAddr = (unsigned)__cvta_generic_to_shared(sPre);
    const unsigned* preH = g_pre1 + (size_t)h * SEGS * 64;
    __syncthreads();

    for (int tile = blockIdx.x; tile < NTILES; tile += gridDim.x) {
        const int row0 = tile * 128;
        const int rows = min(128, N_NODES - row0);

        if (tid < 128) sSeg[tid] = (tid < rows) ? index[row0 + tid] : 0;
        load_rows_h(sA, fea + (size_t)row0 * 128, rows, tid);
        __syncthreads();

        // gather pre1 rows via cp.async (overlaps GEMM below)
#pragma unroll
        for (int i = 0; i < 8; i++) {
            int v = i * 256 + tid;
            int r = v >> 4, ch = v & 15;
            cpa16(sPreAddr + (unsigned)(r * LH2 + ch * 4) * 4,
                  preH + (size_t)sSeg[r] * 64 + ch * 4);
        }
        asm volatile("cp.async.commit_group;" ::: "memory");

        float acc[2][8][4];
#pragma unroll
        for (int x1 = 0; x1 < 2; x1++)
#pragma unroll
            for (int x2 = 0; x2 < 8; x2++)
#pragma unroll
                for (int x3 = 0; x3 < 4; x3++) acc[x1][x2][x3] = 0.f;
        gemm128h(sA, sB1, acc, warpRow, warpCol, lane);

        asm volatile("cp.async.wait_group 0;" ::: "memory");
        __syncthreads();

        // alpha[r] = sum_o leaky(acc + pre[seg[r]][o] + b1[o]) * w2[o] + b2
        float p[2][2];
#pragma unroll
        for (int mt = 0; mt < 2; mt++) { p[mt][0] = 0.f; p[mt][1] = 0.f; }
#pragma unroll
        for (int mt = 0; mt < 2; mt++)
#pragma unroll
            for (int nt = 0; nt < 8; nt++) {
                const int c0 = warpCol * 64 + nt * 8 + 2 * t;
                const int rbase = warpRow * 32 + mt * 16 + g;
#pragma unroll
                for (int j = 0; j < 2; j++) {
                    unsigned pw = sPre[(rbase + j * 8) * LH2 + (c0 >> 1)];
                    float2 pf = __half22float2(*reinterpret_cast<__half2*>(&pw));
                    float x0 = acc[mt][nt][j * 2 + 0] + pf.x + sb1[c0];
                    float x1 = acc[mt][nt][j * 2 + 1] + pf.y + sb1[c0 + 1];
                    x0 = (x0 >= 0.f) ? x0 : SLOPE * x0;
                    x1 = (x1 >= 0.f) ? x1 : SLOPE * x1;
                    p[mt][j] += x0 * sw2[c0] + x1 * sw2[c0 + 1];
                }
            }
#pragma unroll
        for (int mt = 0; mt < 2; mt++)
#pragma unroll
            for (int j = 0; j < 2; j++) {
                float v = p[mt][j];
                v += __shfl_xor_sync(0xffffffffu, v, 1);
                v += __shfl_xor_sync(0xffffffffu, v, 2);
                if ((lane & 3) == 0)
                    sPart[(warpRow * 32 + mt * 16 + g + j * 8) * 2 + warpCol] = v;
            }
        __syncthreads();
        if (tid < rows) {
            float av = sPart[tid * 2] + sPart[tid * 2 + 1] + ba2v;
            float e = expf(av);
            g_e[(size_t)(row0 + tid) * 4 + h] = e;
            atomicAdd(&g_denom[sSeg[tid] * 4 + h], e);
        }
        __syncthreads();
    }
}

// ---------------- kernel 2: GEMM1 + alpha-weighted segment-sum of hidden ----
// Epilogue stages alpha*leaky(h) as fp16 in a DEDICATED buffer (no sA alias):
// single pass, 3 syncs/tile, half the staging bytes.
__global__ void __launch_bounds__(256, 2)
k_msg2(const float* __restrict__ fea,
       const float* __restrict__ Wm1, const float* __restrict__ bm1,
       const int* __restrict__ index) {
    extern __shared__ unsigned smem_u[];
    unsigned* sA    = smem_u;                    // fea tile
    unsigned* sB1   = sA + 128 * LH2;            // W1
    unsigned* sOutH = sB1 + 128 * LH2;           // [128][68] half2 staging
    float* sb1    = (float*)(sOutH + 128 * LH2);
    float* sScale = sb1 + 128;
    int*   sSeg   = (int*)(sScale + 128);

    const int tid  = threadIdx.x;
    const int lane = tid & 31;
    const int warp = tid >> 5;
    const int warpRow = warp >> 1, warpCol = warp & 1;
    const int g = lane >> 2, t = lane & 3;
    const int h = blockIdx.y;
    float* Hh = g_H + (size_t)h * SEGS * 128;

    load_w_h(sB1, Wm1 + (size_t)h * 128 * 128, 128, tid);
    if (tid < 128) sb1[tid] = bm1[h * 128 + tid];
    __syncthreads();

    for (int tile = blockIdx.x; tile < NTILES; tile += gridDim.x) {
        const int row0 = tile * 128;
        const int rows = min(128, N_NODES - row0);

        if (tid < 128) {
            if (tid < rows) {
                int s = index[row0 + tid];
                sSeg[tid] = s;
                sScale[tid] = g_e[(size_t)(row0 + tid) * 4 + h] /
                              (g_denom[s * 4 + h] + 1e-16f);
            } else {
                sSeg[tid] = index[row0 + rows - 1];
                sScale[tid] = 0.f;
            }
        }
        load_rows_h(sA, fea + (size_t)row0 * 128, rows, tid);
        __syncthreads();   // sync 1: sA + sSeg/sScale ready (also guards prev reduce)

        float acc[2][8][4];
#pragma unroll
        for (int x1 = 0; x1 < 2; x1++)
#pragma unroll
            for (int x2 = 0; x2 < 8; x2++)
#pragma unroll
                for (int x3 = 0; x3 < 4; x3++) acc[x1][x2][x3] = 0.f;
        gemm128h(sA, sB1, acc, warpRow, warpCol, lane);

        // single-pass epilogue: alpha * leaky(acc+b1) -> sOutH as half2
#pragma unroll
        for (int mt = 0; mt < 2; mt++)
#pragma unroll
            for (int nt = 0; nt < 8; nt++)
#pragma unroll
                for (int ip = 0; ip < 2; ip++) {
                    int row = warpRow * 32 + mt * 16 + g + ip * 8;
                    int c0 = warpCol * 64 + nt * 8 + 2 * t;
                    float sc = sScale[row];
                    float x0 = acc[mt][nt][ip * 2 + 0] + sb1[c0];
                    float x1 = acc[mt][nt][ip * 2 + 1] + sb1[c0 + 1];
                    x0 = (x0 >= 0.f) ? x0 : SLOPE * x0;
                    x1 = (x1 >= 0.f) ? x1 : SLOPE * x1;
                    sOutH[row * LH2 + (c0 >> 1)] = h2pack(x0 * sc, x1 * sc);
                }
        __syncthreads();   // sync 2: staging visible

        // segmented reduce: thread = column-pair (64) x row-quarter (4)
        {
            const int cp  = tid & 63;          // half2 column index (cols 2cp, 2cp+1)
            const int q   = tid >> 6;          // row quarter
            const int r0q = q * 32;
            float a0 = 0.f, a1 = 0.f;
            int cur = sSeg[r0q];
#pragma unroll 4
            for (int r = 0; r < 32; r++) {
                int s = sSeg[r0q + r];
                if (s != cur) {
                    atomicAdd(&Hh[(size_t)cur * 128 + 2 * cp],     a0);
                    atomicAdd(&Hh[(size_t)cur * 128 + 2 * cp + 1], a1);
                    a0 = 0.f; a1 = 0.f;
                    cur = s;
                }
                unsigned pw = sOutH[(r0q + r) * LH2 + cp];
                float2 pf = __half22float2(*reinterpret_cast<__half2*>(&pw));
                a0 += pf.x; a1 += pf.y;
            }
            atomicAdd(&Hh[(size_t)cur * 128 + 2 * cp],     a0);
            atomicAdd(&Hh[(size_t)cur * 128 + 2 * cp + 1], a1);
        }
        __syncthreads();   // sync 3: reduce done before next tile overwrites
    }
}

// ---------------- kernel 3: out = W2 . H + b2 * indicator ----------------
__global__ void __launch_bounds__(256, 2)
k_out(const float* __restrict__ Wm2, const float* __restrict__ bm2,
      float* __restrict__ out) {
    extern __shared__ unsigned smem_u[];
    unsigned* sA = smem_u;                 // H tile (fp16)
    unsigned* sB = sA + 128 * LH2;         // W2
    float* sb2  = (float*)(sB + 128 * LH2);
    float* sInd = sb2 + 128;

    const int tid  = threadIdx.x;
    const int lane = tid & 31;
    const int warp = tid >> 5;
    const int warpRow = warp >> 1, warpCol = warp & 1;
    const int g = lane >> 2, t = lane & 3;
    const int h  = blockIdx.y;
    const int s0 = blockIdx.x * 128;

    load_w_h(sB, Wm2 + (size_t)h * 128 * 128, 128, tid);
    load_rows_h(sA, g_H + ((size_t)h * SEGS + s0) * 128, 128, tid);
    if (tid < 128) {
        sb2[tid]  = bm2[h * 128 + tid];
        sInd[tid] = (g_denom[(s0 + tid) * 4 + h] > 0.f) ? 1.f : 0.f;
    }
    __syncthreads();

    float acc[2][8][4];
#pragma unroll
    for (int x1 = 0; x1 < 2; x1++)
#pragma unroll
        for (int x2 = 0; x2 < 8; x2++)
#pragma unroll
            for (int x3 = 0; x3 < 4; x3++) acc[x1][x2][x3] = 0.f;
    gemm128h(sA, sB, acc, warpRow, warpCol, lane);

#pragma unroll
    for (int mt = 0; mt < 2; mt++)
#pragma unroll
        for (int nt = 0; nt < 8; nt++)
#pragma unroll
            for (int ip = 0; ip < 2; ip++) {
                int row = warpRow * 32 + mt * 16 + g + ip * 8;
                int c0 = warpCol * 64 + nt * 8 + 2 * t;
                float a = sInd[row];
                float2 v;
                v.x = acc[mt][nt][ip * 2 + 0] + sb2[c0] * a;
                v.y = acc[mt][nt][ip * 2 + 1] + sb2[c0 + 1] * a;
                *reinterpret_cast<float2*>(
                    out + (size_t)(s0 + row) * 512 + h * 128 + c0) = v;
            }
}

// ---------------- launch ----------------
extern "C" void kernel_launch(void* const* d_in, const int* in_sizes, int n_in,
                              void* d_out, int out_size) {
    (void)in_sizes; (void)n_in; (void)out_size;
    const float* fea = (const float*)d_in[0];
    const float* cry = (const float*)d_in[1];
    const float* Wm1 = (const float*)d_in[2];
    const float* bm1 = (const float*)d_in[3];
    const float* Wm2 = (const float*)d_in[4];
    const float* bm2 = (const float*)d_in[5];
    const float* Wa1 = (const float*)d_in[6];
    const float* ba1 = (const float*)d_in[7];
    const float* Wa2 = (const float*)d_in[8];
    const float* ba2 = (const float*)d_in[9];
    const int*   idx = (const int*)d_in[10];
    float* out = (float*)d_out;

    const size_t smem_pre   = (size_t)(2 * 128 * LH2) * 4;
    const size_t smem_alpha = (size_t)(3 * 128 * LH2 + 128 + 128 + 256 + 128) * 4;
    const size_t smem_msg   = (size_t)(3 * 128 * LH2 + 128 + 128 + 128) * 4;
    const size_t smem_out   = (size_t)(2 * 128 * LH2 + 128 + 128) * 4;
    cudaFuncSetAttribute(k_pre,   cudaFuncAttributeMaxDynamicSharedMemorySize, (int)smem_pre);
    cudaFuncSetAttribute(k_alpha, cudaFuncAttributeMaxDynamicSharedMemorySize, (int)smem_alpha);
    cudaFuncSetAttribute(k_msg2,  cudaFuncAttributeMaxDynamicSharedMemorySize, (int)smem_msg);
    cudaFuncSetAttribute(k_out,   cudaFuncAttributeMaxDynamicSharedMemorySize, (int)smem_out);

    k_init<<<2048, 512>>>();
    k_pre<<<dim3(SEGS / 128, 4), 256, smem_pre>>>(cry, Wa1);
    k_alpha<<<dim3(74, 4), 256, smem_alpha>>>(fea, Wa1, ba1, Wa2, ba2, idx);
    k_msg2<<<dim3(74, 4), 256, smem_msg>>>(fea, Wm1, bm1, idx);
    k_out<<<dim3(SEGS / 128, 4), 256, smem_out>>>(Wm2, bm2, out);
}

// round 15
// speedup vs baseline: 1.5912x; 1.0741x over previous
#include <cuda_runtime.h>
#include <cuda_fp16.h>
#include <cstdint>

#define N_NODES 200000
#define SEGS    16384
#define NTILES  ((N_NODES + 127) / 128)   // 1563
#define FEAPAD  (NTILES * 128)            // 200064 rows (padded)
#define HEADS   4
#define LH2     68     // smem row stride in half2 units (272 B)
#define SLOPE   0.01f

// ---------------- device scratch ----------------
__device__ float    g_e[N_NODES * HEADS];
__device__ float    g_denom[SEGS * HEADS];
__device__ unsigned g_pre1[HEADS * SEGS * 64];        // fp16x2: W1R . cry per segment
__device__ float    g_H[(size_t)HEADS * SEGS * 128];  // Σ α_n h_n per segment
__device__ __align__(16) unsigned g_feah[(size_t)FEAPAD * 64];  // fea as fp16x2, padded

// ---------------- helpers ----------------
__device__ __forceinline__ unsigned h2pack(float a, float b) {
    unsigned r;
    asm("cvt.rn.f16x2.f32 %0, %2, %1;" : "=r"(r) : "f"(a), "f"(b));
    return r;  // lo = a, hi = b
}

__device__ __forceinline__ void mma_f16(float c[4], const unsigned a[4], const unsigned b[2]) {
    asm volatile(
        "mma.sync.aligned.m16n8k16.row.col.f32.f16.f16.f32 "
        "{%0,%1,%2,%3}, {%4,%5,%6,%7}, {%8,%9}, {%0,%1,%2,%3};\n"
        : "+f"(c[0]), "+f"(c[1]), "+f"(c[2]), "+f"(c[3])
        : "r"(a[0]), "r"(a[1]), "r"(a[2]), "r"(a[3]), "r"(b[0]), "r"(b[1]));
}

__device__ __forceinline__ void ldsm_x4(unsigned &r0, unsigned &r1, unsigned &r2, unsigned &r3,
                                        unsigned addr) {
    asm volatile("ldmatrix.sync.aligned.m8n8.x4.shared.b16 {%0,%1,%2,%3}, [%4];"
                 : "=r"(r0), "=r"(r1), "=r"(r2), "=r"(r3) : "r"(addr));
}

__device__ __forceinline__ void cpa16(unsigned saddr, const void* g) {
    asm volatile("cp.async.ca.shared.global [%0], [%1], 16;" :: "r"(saddr), "l"(g) : "memory");
}

// async-load a 128x128 fp16 tile (2048 x 16B chunks) from g_feah, then commit
__device__ __forceinline__ void load_tile_async(unsigned sAaddr, const unsigned* __restrict__ src,
                                                int tid) {
#pragma unroll
    for (int i = 0; i < 8; i++) {
        int v = i * 256 + tid;
        int r = v >> 4, ch = v & 15;
        cpa16(sAaddr + (unsigned)(r * 272 + ch * 16), src + (size_t)r * 64 + ch * 4);
    }
    asm volatile("cp.async.commit_group;" ::: "memory");
}

// 128x128x128 GEMM: C[r][o] += sum_k A[r][k]*B[o][k]; fp16 half2-packed smem,
// row stride 272B. 8 warps (4x2), warp tile 32x64. Fragments via ldmatrix.x4.
__device__ __forceinline__ void gemm128h(const unsigned* sA, const unsigned* sB,
                                         float (&acc)[2][8][4],
                                         int warpRow, int warpCol, int lane) {
    const unsigned sAb = (unsigned)__cvta_generic_to_shared(sA);
    const unsigned sBb = (unsigned)__cvta_generic_to_shared(sB);
    const int l15 = lane & 15, l7 = lane & 7;
    unsigned aAddr[2], bAddr[4];
#pragma unroll
    for (int mt = 0; mt < 2; mt++)
        aAddr[mt] = sAb + (unsigned)((warpRow * 32 + mt * 16 + l15) * 272 + (lane >> 4) * 16);
#pragma unroll
    for (int p = 0; p < 4; p++)
        bAddr[p] = sBb + (unsigned)((warpCol * 64 + p * 16 + l7 + ((lane & 16) >> 1)) * 272
                                    + ((lane >> 3) & 1) * 16);
#pragma unroll
    for (int ks = 0; ks < 8; ks++) {
        unsigned a[2][4], b[8][2];
#pragma unroll
        for (int mt = 0; mt < 2; mt++) {
            ldsm_x4(a[mt][0], a[mt][1], a[mt][2], a[mt][3], aAddr[mt]);
            aAddr[mt] += 32;
        }
#pragma unroll
        for (int p = 0; p < 4; p++) {
            ldsm_x4(b[2 * p][0], b[2 * p][1], b[2 * p + 1][0], b[2 * p + 1][1], bAddr[p]);
            bAddr[p] += 32;
        }
#pragma unroll
        for (int mt = 0; mt < 2; mt++)
#pragma unroll
            for (int nt = 0; nt < 8; nt++)
                mma_f16(acc[mt][nt], a[mt], b[nt]);
    }
}

// load [rows<=128,128] f32 -> fp16 smem tile (256 threads)  [k_pre/k_out only]
__device__ __forceinline__ void load_rows_h(unsigned* dst, const float* __restrict__ src,
                                            int rows, int tid) {
#pragma unroll
    for (int i = 0; i < 16; i++) {
        int v = i * 256 + tid;
        int r = v >> 5, c4 = v & 31;
        float4 val = make_float4(0.f, 0.f, 0.f, 0.f);
        if (r < rows) val = reinterpret_cast<const float4*>(src)[r * 32 + c4];
        uint2 u = make_uint2(h2pack(val.x, val.y), h2pack(val.z, val.w));
        *reinterpret_cast<uint2*>(dst + r * LH2 + c4 * 2) = u;
    }
}

__device__ __forceinline__ void load_w_h(unsigned* dst, const float* __restrict__ src,
                                         int srcStride, int tid) {
#pragma unroll
    for (int i = 0; i < 16; i++) {
        int v = i * 256 + tid;
        int r = v >> 5, c4 = v & 31;
        float4 val = *reinterpret_cast<const float4*>(src + (size_t)r * srcStride + c4 * 4);
        uint2 u = make_uint2(h2pack(val.x, val.y), h2pack(val.z, val.w));
        *reinterpret_cast<uint2*>(dst + r * LH2 + c4 * 2) = u;
    }
}

// ---------------- kernel 0: init (fea->fp16 + zero g_H + denom) ----------------
__global__ void k_init(const float* __restrict__ fea) {
    int i = blockIdx.x * blockDim.x + threadIdx.x;
    int stride = gridDim.x * blockDim.x;
    const int totF4 = FEAPAD * 32;       // float4 units per padded fea
    const int nF4   = N_NODES * 32;
    for (int j = i; j < totF4; j += stride) {
        float4 v = make_float4(0.f, 0.f, 0.f, 0.f);
        if (j < nF4) v = reinterpret_cast<const float4*>(fea)[j];
        reinterpret_cast<uint2*>(g_feah)[j] =
            make_uint2(h2pack(v.x, v.y), h2pack(v.z, v.w));
    }
    int nH4 = (HEADS * SEGS * 128) >> 2;
    for (int j = i; j < nH4; j += stride)
        reinterpret_cast<float4*>(g_H)[j] = make_float4(0.f, 0.f, 0.f, 0.f);
    for (int j = i; j < SEGS * HEADS; j += stride) g_denom[j] = 0.f;
}

// ---------------- kernel pre: pre1[h][s] = W1R . cry[s] (fp16) ----------------
__global__ void __launch_bounds__(256, 1)
k_pre(const float* __restrict__ cry, const float* __restrict__ Wa1) {
    extern __shared__ unsigned smem_u[];
    unsigned* sA = smem_u;              // cry tile
    unsigned* sB = sA + 128 * LH2;      // W1R

    const int tid  = threadIdx.x;
    const int lane = tid & 31;
    const int warp = tid >> 5;
    const int warpRow = warp >> 1, warpCol = warp & 1;
    const int g = lane >> 2, t = lane & 3;
    const int h  = blockIdx.y;
    const int s0 = blockIdx.x * 128;

    load_w_h(sB, Wa1 + (size_t)h * 128 * 256 + 128, 256, tid);
    load_w_h(sA, cry + (size_t)s0 * 128, 128, tid);
    __syncthreads();

    float acc[2][8][4];
#pragma unroll
    for (int x1 = 0; x1 < 2; x1++)
#pragma unroll
        for (int x2 = 0; x2 < 8; x2++)
#pragma unroll
            for (int x3 = 0; x3 < 4; x3++) acc[x1][x2][x3] = 0.f;
    gemm128h(sA, sB, acc, warpRow, warpCol, lane);

#pragma unroll
    for (int mt = 0; mt < 2; mt++)
#pragma unroll
        for (int nt = 0; nt < 8; nt++)
#pragma unroll
            for (int j = 0; j < 2; j++) {
                int row = warpRow * 32 + mt * 16 + g + j * 8;
                int c0  = warpCol * 64 + nt * 8 + 2 * t;
                g_pre1[((size_t)h * SEGS + s0 + row) * 64 + (c0 >> 1)] =
                    h2pack(acc[mt][nt][j * 2 + 0], acc[mt][nt][j * 2 + 1]);
            }
}

// ---------------- kernel 1: alpha GEMM + fused exp/denom (pipelined) --------
__global__ void __launch_bounds__(256, 2)
k_alpha(const float* __restrict__ Wa1, const float* __restrict__ ba1,
        const float* __restrict__ Wa2, const float* __restrict__ ba2,
        const int* __restrict__ index) {
    extern __shared__ unsigned smem_u[];
    unsigned* sA   = smem_u;                  // fea tile (fp16)
    unsigned* sB1  = sA + 128 * LH2;          // W1L
    unsigned* sPre = sB1 + 128 * LH2;         // gathered pre1 (fp16)
    float* sb1   = (float*)(sPre + 128 * LH2);
    float* sw2   = sb1 + 128;
    float* sPart = sw2 + 128;                 // 256
    int*   sSeg  = (int*)(sPart + 256);       // 128

    const int tid  = threadIdx.x;
    const int lane = tid & 31;
    const int warp = tid >> 5;
    const int warpRow = warp >> 1, warpCol = warp & 1;
    const int g = lane >> 2, t = lane & 3;
    const int h = blockIdx.y;

    load_w_h(sB1, Wa1 + (size_t)h * 128 * 256, 256, tid);
    if (tid < 128) {
        sb1[tid] = ba1[h * 128 + tid];
        sw2[tid] = Wa2[h * 128 + tid];
    }
    const float ba2v = ba2[h];
    const unsigned sAaddr   = (unsigned)__cvta_generic_to_shared(sA);
    const unsigned sPreAddr = (unsigned)__cvta_generic_to_shared(sPre);
    const unsigned* preH = g_pre1 + (size_t)h * SEGS * 64;

    int tile = blockIdx.x;
    load_tile_async(sAaddr, g_feah + (size_t)tile * 128 * 64, tid);

    for (; tile < NTILES; tile += gridDim.x) {
        const int row0 = tile * 128;
        const int rows = min(128, N_NODES - row0);

        int myseg = 0;
        if (tid < 128 && tid < rows) myseg = index[row0 + tid];

        asm volatile("cp.async.wait_group 0;" ::: "memory");
        __syncthreads();                       // S1: fea ready; prev tile fully done
        if (tid < 128) sSeg[tid] = myseg;
        __syncthreads();                       // S2: sSeg visible for gather

        // gather pre1 rows via cp.async (G1, overlaps GEMM)
#pragma unroll
        for (int i = 0; i < 8; i++) {
            int v = i * 256 + tid;
            int r = v >> 4, ch = v & 15;
            cpa16(sPreAddr + (unsigned)(r * 272 + ch * 16),
                  preH + (size_t)sSeg[r] * 64 + ch * 4);
        }
        asm volatile("cp.async.commit_group;" ::: "memory");

        float acc[2][8][4];
#pragma unroll
        for (int x1 = 0; x1 < 2; x1++)
#pragma unroll
            for (int x2 = 0; x2 < 8; x2++)
#pragma unroll
                for (int x3 = 0; x3 < 4; x3++) acc[x1][x2][x3] = 0.f;
        gemm128h(sA, sB1, acc, warpRow, warpCol, lane);
        __syncthreads();                       // S3: sA free for prefetch

        const int tn = tile + gridDim.x;
        if (tn < NTILES) {
            load_tile_async(sAaddr, g_feah + (size_t)tn * 128 * 64, tid);   // G2
            asm volatile("cp.async.wait_group 1;" ::: "memory");            // G1 done
        } else {
            asm volatile("cp.async.wait_group 0;" ::: "memory");
        }
        __syncthreads();                       // S4: sPre visible

        // alpha[r] = sum_o leaky(acc + pre[seg[r]][o] + b1[o]) * w2[o] + b2
        float p[2][2];
#pragma unroll
        for (int mt = 0; mt < 2; mt++) { p[mt][0] = 0.f; p[mt][1] = 0.f; }
#pragma unroll
        for (int mt = 0; mt < 2; mt++)
#pragma unroll
            for (int nt = 0; nt < 8; nt++) {
                const int c0 = warpCol * 64 + nt * 8 + 2 * t;
                const int rbase = warpRow * 32 + mt * 16 + g;
#pragma unroll
                for (int j = 0; j < 2; j++) {
                    unsigned pw = sPre[(rbase + j * 8) * LH2 + (c0 >> 1)];
                    float2 pf = __half22float2(*reinterpret_cast<__half2*>(&pw));
                    float x0 = acc[mt][nt][j * 2 + 0] + pf.x + sb1[c0];
                    float x1 = acc[mt][nt][j * 2 + 1] + pf.y + sb1[c0 + 1];
                    x0 = (x0 >= 0.f) ? x0 : SLOPE * x0;
                    x1 = (x1 >= 0.f) ? x1 : SLOPE * x1;
                    p[mt][j] += x0 * sw2[c0] + x1 * sw2[c0 + 1];
                }
            }
#pragma unroll
        for (int mt = 0; mt < 2; mt++)
#pragma unroll
            for (int j = 0; j < 2; j++) {
                float v = p[mt][j];
                v += __shfl_xor_sync(0xffffffffu, v, 1);
                v += __shfl_xor_sync(0xffffffffu, v, 2);
                if ((lane & 3) == 0)
                    sPart[(warpRow * 32 + mt * 16 + g + j * 8) * 2 + warpCol] = v;
            }
        __syncthreads();                       // S5: sPart visible
        if (tid < rows) {
            float av = sPart[tid * 2] + sPart[tid * 2 + 1] + ba2v;
            float e = expf(av);
            g_e[(size_t)(row0 + tid) * 4 + h] = e;
            atomicAdd(&g_denom[sSeg[tid] * 4 + h], e);
        }
        // no trailing sync: S1 of next iter guards reuse
    }
}

// ---------------- kernel 2: GEMM1 + alpha-weighted segment-sum (pipelined) --
__global__ void __launch_bounds__(256, 2)
k_msg2(const float* __restrict__ Wm1, const float* __restrict__ bm1,
       const int* __restrict__ index) {
    extern __shared__ unsigned smem_u[];
    unsigned* sA    = smem_u;                    // fea tile (fp16)
    unsigned* sB1   = sA + 128 * LH2;            // W1
    unsigned* sOutH = sB1 + 128 * LH2;           // [128][68] half2 staging
    float* sb1    = (float*)(sOutH + 128 * LH2);
    float* sScale = sb1 + 128;
    int*   sSeg   = (int*)(sScale + 128);

    const int tid  = threadIdx.x;
    const int lane = tid & 31;
    const int warp = tid >> 5;
    const int warpRow = warp >> 1, warpCol = warp & 1;
    const int g = lane >> 2, t = lane & 3;
    const int h = blockIdx.y;
    float* Hh = g_H + (size_t)h * SEGS * 128;

    load_w_h(sB1, Wm1 + (size_t)h * 128 * 128, 128, tid);
    if (tid < 128) sb1[tid] = bm1[h * 128 + tid];
    const unsigned sAaddr = (unsigned)__cvta_generic_to_shared(sA);

    int tile = blockIdx.x;
    load_tile_async(sAaddr, g_feah + (size_t)tile * 128 * 64, tid);

    for (; tile < NTILES; tile += gridDim.x) {
        const int row0 = tile * 128;
        const int rows = min(128, N_NODES - row0);

        int myseg = 0; float mysc = 0.f;
        if (tid < 128) {
            if (tid < rows) {
                myseg = index[row0 + tid];
                mysc  = g_e[(size_t)(row0 + tid) * 4 + h] /
                        (g_denom[myseg * 4 + h] + 1e-16f);
            } else {
                myseg = index[row0 + rows - 1];
            }
        }

        asm volatile("cp.async.wait_group 0;" ::: "memory");
        __syncthreads();                       // S1: fea ready; prev reduce done
        if (tid < 128) { sSeg[tid] = myseg; sScale[tid] = mysc; }

        float acc[2][8][4];
#pragma unroll
        for (int x1 = 0; x1 < 2; x1++)
#pragma unroll
            for (int x2 = 0; x2 < 8; x2++)
#pragma unroll
                for (int x3 = 0; x3 < 4; x3++) acc[x1][x2][x3] = 0.f;
        gemm128h(sA, sB1, acc, warpRow, warpCol, lane);
        __syncthreads();                       // S2: sA free; sSeg/sScale visible

        const int tn = tile + gridDim.x;
        if (tn < NTILES)
            load_tile_async(sAaddr, g_feah + (size_t)tn * 128 * 64, tid);  // hides under tail

        // single-pass epilogue: alpha * leaky(acc+b1) -> sOutH as half2
#pragma unroll
        for (int mt = 0; mt < 2; mt++)
#pragma unroll
            for (int nt = 0; nt < 8; nt++)
#pragma unroll
                for (int ip = 0; ip < 2; ip++) {
                    int row = warpRow * 32 + mt * 16 + g + ip * 8;
                    int c0 = warpCol * 64 + nt * 8 + 2 * t;
                    float sc = sScale[row];
                    float x0 = acc[mt][nt][ip * 2 + 0] + sb1[c0];
                    float x1 = acc[mt][nt][ip * 2 + 1] + sb1[c0 + 1];
                    x0 = (x0 >= 0.f) ? x0 : SLOPE * x0;
                    x1 = (x1 >= 0.f) ? x1 : SLOPE * x1;
                    sOutH[row * LH2 + (c0 >> 1)] = h2pack(x0 * sc, x1 * sc);
                }
        __syncthreads();                       // S3: staging visible

        // segmented reduce: thread = column-pair (64) x row-quarter (4)
        {
            const int cp  = tid & 63;
            const int q   = tid >> 6;
            const int r0q = q * 32;
            float a0 = 0.f, a1 = 0.f;
            int cur = sSeg[r0q];
#pragma unroll 4
            for (int r = 0; r < 32; r++) {
                int s = sSeg[r0q + r];
                if (s != cur) {
                    atomicAdd(&Hh[(size_t)cur * 128 + 2 * cp],     a0);
                    atomicAdd(&Hh[(size_t)cur * 128 + 2 * cp + 1], a1);
                    a0 = 0.f; a1 = 0.f;
                    cur = s;
                }
                unsigned pw = sOutH[(r0q + r) * LH2 + cp];
                float2 pf = __half22float2(*reinterpret_cast<__half2*>(&pw));
                a0 += pf.x; a1 += pf.y;
            }
            atomicAdd(&Hh[(size_t)cur * 128 + 2 * cp],     a0);
            atomicAdd(&Hh[(size_t)cur * 128 + 2 * cp + 1], a1);
        }
        // no trailing sync: S1 of next iter guards reuse
    }
}

// ---------------- kernel 3: out = W2 . H + b2 * indicator ----------------
__global__ void __launch_bounds__(256, 2)
k_out(const float* __restrict__ Wm2, const float* __restrict__ bm2,
      float* __restrict__ out) {
    extern __shared__ unsigned smem_u[];
    unsigned* sA = smem_u;                 // H tile (fp16)
    unsigned* sB = sA + 128 * LH2;         // W2
    float* sb2  = (float*)(sB + 128 * LH2);
    float* sInd = sb2 + 128;

    const int tid  = threadIdx.x;
    const int lane = tid & 31;
    const int warp = tid >> 5;
    const int warpRow = warp >> 1, warpCol = warp & 1;
    const int g = lane >> 2, t = lane & 3;
    const int h  = blockIdx.y;
    const int s0 = blockIdx.x * 128;

    load_w_h(sB, Wm2 + (size_t)h * 128 * 128, 128, tid);
    load_rows_h(sA, g_H + ((size_t)h * SEGS + s0) * 128, 128, tid);
    if (tid < 128) {
        sb2[tid]  = bm2[h * 128 + tid];
        sInd[tid] = (g_denom[(s0 + tid) * 4 + h] > 0.f) ? 1.f : 0.f;
    }
    __syncthreads();

    float acc[2][8][4];
#pragma unroll
    for (int x1 = 0; x1 < 2; x1++)
#pragma unroll
        for (int x2 = 0; x2 < 8; x2++)
#pragma unroll
            for (int x3 = 0; x3 < 4; x3++) acc[x1][x2][x3] = 0.f;
    gemm128h(sA, sB, acc, warpRow, warpCol, lane);

#pragma unroll
    for (int mt = 0; mt < 2; mt++)
#pragma unroll
        for (int nt = 0; nt < 8; nt++)
#pragma unroll
            for (int ip = 0; ip < 2; ip++) {
                int row = warpRow * 32 + mt * 16 + g + ip * 8;
                int c0 = warpCol * 64 + nt * 8 + 2 * t;
                float a = sInd[row];
                float2 v;
                v.x = acc[mt][nt][ip * 2 + 0] + sb2[c0] * a;
                v.y = acc[mt][nt][ip * 2 + 1] + sb2[c0 + 1] * a;
                *reinterpret_cast<float2*>(
                    out + (size_t)(s0 + row) * 512 + h * 128 + c0) = v;
            }
}

// ---------------- launch ----------------
extern "C" void kernel_launch(void* const* d_in, const int* in_sizes, int n_in,
                              void* d_out, int out_size) {
    (void)in_sizes; (void)n_in; (void)out_size;
    const float* fea = (const float*)d_in[0];
    const float* cry = (const float*)d_in[1];
    const float* Wm1 = (const float*)d_in[2];
    const float* bm1 = (const float*)d_in[3];
    const float* Wm2 = (const float*)d_in[4];
    const float* bm2 = (const float*)d_in[5];
    const float* Wa1 = (const float*)d_in[6];
    const float* ba1 = (const float*)d_in[7];
    const float* Wa2 = (const float*)d_in[8];
    const float* ba2 = (const float*)d_in[9];
    const int*   idx = (const int*)d_in[10];
    float* out = (float*)d_out;

    const size_t smem_pre   = (size_t)(2 * 128 * LH2) * 4;
    const size_t smem_alpha = (size_t)(3 * 128 * LH2 + 128 + 128 + 256 + 128) * 4;
    const size_t smem_msg   = (size_t)(3 * 128 * LH2 + 128 + 128 + 128) * 4;
    const size_t smem_out   = (size_t)(2 * 128 * LH2 + 128 + 128) * 4;
    cudaFuncSetAttribute(k_pre,   cudaFuncAttributeMaxDynamicSharedMemorySize, (int)smem_pre);
    cudaFuncSetAttribute(k_alpha, cudaFuncAttributeMaxDynamicSharedMemorySize, (int)smem_alpha);
    cudaFuncSetAttribute(k_msg2,  cudaFuncAttributeMaxDynamicSharedMemorySize, (int)smem_msg);
    cudaFuncSetAttribute(k_out,   cudaFuncAttributeMaxDynamicSharedMemorySize, (int)smem_out);

    k_init<<<2048, 512>>>(fea);
    k_pre<<<dim3(SEGS / 128, 4), 256, smem_pre>>>(cry, Wa1);
    k_alpha<<<dim3(74, 4), 256, smem_alpha>>>(Wa1, ba1, Wa2, ba2, idx);
    k_msg2<<<dim3(74, 4), 256, smem_msg>>>(Wm1, bm1, idx);
    k_out<<<dim3(SEGS / 128, 4), 256, smem_out>>>(Wm2, bm2, out);
}

// round 16
// speedup vs baseline: 1.7617x; 1.1072x over previous
#include <cuda_runtime.h>
#include <cuda_fp16.h>
#include <cstdint>

#define N_NODES 200000
#define SEGS    16384
#define NTILES  ((N_NODES + 127) / 128)   // 1563
#define FEAPAD  (NTILES * 128)            // 200064 rows (padded)
#define HEADS   4
#define LH2     68     // smem row stride in half2 units (272 B)
#define SLOPE   0.01f

// ---------------- device scratch ----------------
__device__ float    g_denom[SEGS * HEADS];
__device__ unsigned g_pre1[HEADS * SEGS * 64];        // fp16x2: W1R . cry per segment
__device__ float    g_H[(size_t)HEADS * SEGS * 128];  // Σ e_n h_n per segment
__device__ __align__(16) unsigned g_feah[(size_t)FEAPAD * 64];  // fea as fp16x2, padded

// ---------------- helpers ----------------
__device__ __forceinline__ unsigned h2pack(float a, float b) {
    unsigned r;
    asm("cvt.rn.f16x2.f32 %0, %2, %1;" : "=r"(r) : "f"(a), "f"(b));
    return r;  // lo = a, hi = b
}

__device__ __forceinline__ void mma_f16(float c[4], const unsigned a[4], const unsigned b[2]) {
    asm volatile(
        "mma.sync.aligned.m16n8k16.row.col.f32.f16.f16.f32 "
        "{%0,%1,%2,%3}, {%4,%5,%6,%7}, {%8,%9}, {%0,%1,%2,%3};\n"
        : "+f"(c[0]), "+f"(c[1]), "+f"(c[2]), "+f"(c[3])
        : "r"(a[0]), "r"(a[1]), "r"(a[2]), "r"(a[3]), "r"(b[0]), "r"(b[1]));
}

__device__ __forceinline__ void ldsm_x4(unsigned &r0, unsigned &r1, unsigned &r2, unsigned &r3,
                                        unsigned addr) {
    asm volatile("ldmatrix.sync.aligned.m8n8.x4.shared.b16 {%0,%1,%2,%3}, [%4];"
                 : "=r"(r0), "=r"(r1), "=r"(r2), "=r"(r3) : "r"(addr));
}

__device__ __forceinline__ void cpa16(unsigned saddr, const void* g) {
    asm volatile("cp.async.ca.shared.global [%0], [%1], 16;" :: "r"(saddr), "l"(g) : "memory");
}

// async-load a 128x128 fp16 tile (2048 x 16B chunks) from g_feah, then commit
__device__ __forceinline__ void load_tile_async(unsigned sAaddr, const unsigned* __restrict__ src,
                                                int tid) {
#pragma unroll
    for (int i = 0; i < 8; i++) {
        int v = i * 256 + tid;
        int r = v >> 4, ch = v & 15;
        cpa16(sAaddr + (unsigned)(r * 272 + ch * 16), src + (size_t)r * 64 + ch * 4);
    }
    asm volatile("cp.async.commit_group;" ::: "memory");
}

// 128x128x128 GEMM: C[r][o] += sum_k A[r][k]*B[o][k]; fp16 half2-packed smem,
// row stride 272B. 8 warps (4x2), warp tile 32x64. Fragments via ldmatrix.x4.
__device__ __forceinline__ void gemm128h(const unsigned* sA, const unsigned* sB,
                                         float (&acc)[2][8][4],
                                         int warpRow, int warpCol, int lane) {
    const unsigned sAb = (unsigned)__cvta_generic_to_shared(sA);
    const unsigned sBb = (unsigned)__cvta_generic_to_shared(sB);
    const int l15 = lane & 15, l7 = lane & 7;
    unsigned aAddr[2], bAddr[4];
#pragma unroll
    for (int mt = 0; mt < 2; mt++)
        aAddr[mt] = sAb + (unsigned)((warpRow * 32 + mt * 16 + l15) * 272 + (lane >> 4) * 16);
#pragma unroll
    for (int p = 0; p < 4; p++)
        bAddr[p] = sBb + (unsigned)((warpCol * 64 + p * 16 + l7 + ((lane & 16) >> 1)) * 272
                                    + ((lane >> 3) & 1) * 16);
#pragma unroll
    for (int ks = 0; ks < 8; ks++) {
        unsigned a[2][4], b[8][2];
#pragma unroll
        for (int mt = 0; mt < 2; mt++) {
            ldsm_x4(a[mt][0], a[mt][1], a[mt][2], a[mt][3], aAddr[mt]);
            aAddr[mt] += 32;
        }
#pragma unroll
        for (int p = 0; p < 4; p++) {
            ldsm_x4(b[2 * p][0], b[2 * p][1], b[2 * p + 1][0], b[2 * p + 1][1], bAddr[p]);
            bAddr[p] += 32;
        }
#pragma unroll
        for (int mt = 0; mt < 2; mt++)
#pragma unroll
            for (int nt = 0; nt < 8; nt++)
                mma_f16(acc[mt][nt], a[mt], b[nt]);
    }
}

// load [128,128] f32 -> fp16 smem tile with per-row scale (256 threads)
__device__ __forceinline__ void load_rows_scaled(unsigned* dst, const float* __restrict__ src,
                                                 const float* sRcp, int tid) {
#pragma unroll
    for (int i = 0; i < 16; i++) {
        int v = i * 256 + tid;
        int r = v >> 5, c4 = v & 31;
        float4 val = reinterpret_cast<const float4*>(src)[r * 32 + c4];
        float sc = sRcp[r];
        uint2 u = make_uint2(h2pack(val.x * sc, val.y * sc),
                             h2pack(val.z * sc, val.w * sc));
        *reinterpret_cast<uint2*>(dst + r * LH2 + c4 * 2) = u;
    }
}

__device__ __forceinline__ void load_w_h(unsigned* dst, const float* __restrict__ src,
                                         int srcStride, int tid) {
#pragma unroll
    for (int i = 0; i < 16; i++) {
        int v = i * 256 + tid;
        int r = v >> 5, c4 = v & 31;
        float4 val = *reinterpret_cast<const float4*>(src + (size_t)r * srcStride + c4 * 4);
        uint2 u = make_uint2(h2pack(val.x, val.y), h2pack(val.z, val.w));
        *reinterpret_cast<uint2*>(dst + r * LH2 + c4 * 2) = u;
    }
}

// ---------------- kernel 0: init (fea->fp16 + zero g_H + denom) ----------------
__global__ void k_init(const float* __restrict__ fea) {
    int i = blockIdx.x * blockDim.x + threadIdx.x;
    int stride = gridDim.x * blockDim.x;
    const int totF4 = FEAPAD * 32;
    const int nF4   = N_NODES * 32;
    for (int j = i; j < totF4; j += stride) {
        float4 v = make_float4(0.f, 0.f, 0.f, 0.f);
        if (j < nF4) v = reinterpret_cast<const float4*>(fea)[j];
        reinterpret_cast<uint2*>(g_feah)[j] =
            make_uint2(h2pack(v.x, v.y), h2pack(v.z, v.w));
    }
    int nH4 = (HEADS * SEGS * 128) >> 2;
    for (int j = i; j < nH4; j += stride)
        reinterpret_cast<float4*>(g_H)[j] = make_float4(0.f, 0.f, 0.f, 0.f);
    for (int j = i; j < SEGS * HEADS; j += stride) g_denom[j] = 0.f;
}

// ---------------- kernel pre: pre1[h][s] = W1R . cry[s] (fp16) ----------------
__global__ void __launch_bounds__(256, 1)
k_pre(const float* __restrict__ cry, const float* __restrict__ Wa1) {
    extern __shared__ unsigned smem_u[];
    unsigned* sA = smem_u;              // cry tile
    unsigned* sB = sA + 128 * LH2;      // W1R

    const int tid  = threadIdx.x;
    const int lane = tid & 31;
    const int warp = tid >> 5;
    const int warpRow = warp >> 1, warpCol = warp & 1;
    const int g = lane >> 2, t = lane & 3;
    const int h  = blockIdx.y;
    const int s0 = blockIdx.x * 128;

    load_w_h(sB, Wa1 + (size_t)h * 128 * 256 + 128, 256, tid);
    // cry tile load (f32 -> fp16)
#pragma unroll
    for (int i = 0; i < 16; i++) {
        int v = i * 256 + tid;
        int r = v >> 5, c4 = v & 31;
        float4 val = reinterpret_cast<const float4*>(cry + (size_t)s0 * 128)[r * 32 + c4];
        uint2 u = make_uint2(h2pack(val.x, val.y), h2pack(val.z, val.w));
        *reinterpret_cast<uint2*>(sA + r * LH2 + c4 * 2) = u;
    }
    __syncthreads();

    float acc[2][8][4];
#pragma unroll
    for (int x1 = 0; x1 < 2; x1++)
#pragma unroll
        for (int x2 = 0; x2 < 8; x2++)
#pragma unroll
            for (int x3 = 0; x3 < 4; x3++) acc[x1][x2][x3] = 0.f;
    gemm128h(sA, sB, acc, warpRow, warpCol, lane);

#pragma unroll
    for (int mt = 0; mt < 2; mt++)
#pragma unroll
        for (int nt = 0; nt < 8; nt++)
#pragma unroll
            for (int j = 0; j < 2; j++) {
                int row = warpRow * 32 + mt * 16 + g + j * 8;
                int c0  = warpCol * 64 + nt * 8 + 2 * t;
                g_pre1[((size_t)h * SEGS + s0 + row) * 64 + (c0 >> 1)] =
                    h2pack(acc[mt][nt][j * 2 + 0], acc[mt][nt][j * 2 + 1]);
            }
}

// ---------------- kernel 1 (fused): alpha/e + e-weighted message accumulation -
// Per tile: GEMM_a -> e=exp(alpha) (denom atomic), GEMM_m -> stage e*leaky(h)
// into sA -> segmented reduce into g_H.  Normalization deferred to k_out.
__global__ void __launch_bounds__(256, 2)
k_am(const float* __restrict__ Wa1, const float* __restrict__ ba1,
     const float* __restrict__ Wa2, const float* __restrict__ ba2,
     const float* __restrict__ Wm1, const float* __restrict__ bm1,
     const int* __restrict__ index) {
    extern __shared__ unsigned smem_u[];
    unsigned* sA   = smem_u;                   // fea tile / staging
    unsigned* sW1a = sA + 128 * LH2;           // W_a1 left half
    unsigned* sW1m = sW1a + 128 * LH2;         // W_m1
    float* sb1a   = (float*)(sW1m + 128 * LH2);
    float* sw2    = sb1a + 128;
    float* sb1m   = sw2 + 128;
    float* sPart  = sb1m + 128;                // 256
    float* sScale = sPart + 256;               // 128 (e per row)
    int*   sSeg   = (int*)(sScale + 128);      // 128

    const int tid  = threadIdx.x;
    const int lane = tid & 31;
    const int warp = tid >> 5;
    const int warpRow = warp >> 1, warpCol = warp & 1;
    const int g = lane >> 2, t = lane & 3;
    const int h = blockIdx.y;
    float* Hh = g_H + (size_t)h * SEGS * 128;
    const unsigned* preH = g_pre1 + (size_t)h * SEGS * 64;

    load_w_h(sW1a, Wa1 + (size_t)h * 128 * 256, 256, tid);
    load_w_h(sW1m, Wm1 + (size_t)h * 128 * 128, 128, tid);
    if (tid < 128) {
        sb1a[tid] = ba1[h * 128 + tid];
        sw2[tid]  = Wa2[h * 128 + tid];
        sb1m[tid] = bm1[h * 128 + tid];
    }
    const float ba2v = ba2[h];
    const unsigned sAaddr = (unsigned)__cvta_generic_to_shared(sA);

    int tile = blockIdx.x;
    load_tile_async(sAaddr, g_feah + (size_t)tile * 128 * 64, tid);

    for (; tile < NTILES; tile += gridDim.x) {
        const int row0 = tile * 128;
        const int rows = min(128, N_NODES - row0);

        int myseg = 0;
        if (tid < 128)
            myseg = (tid < rows) ? index[row0 + tid] : index[row0 + rows - 1];

        asm volatile("cp.async.wait_group 0;" ::: "memory");
        __syncthreads();                    // S1: fea ready; prev tile done
        if (tid < 128) sSeg[tid] = myseg;
        __syncthreads();                    // S2: sSeg visible

        // ---- GEMM_a ----
        float acc[2][8][4];
#pragma unroll
        for (int x1 = 0; x1 < 2; x1++)
#pragma unroll
            for (int x2 = 0; x2 < 8; x2++)
#pragma unroll
                for (int x3 = 0; x3 < 4; x3++) acc[x1][x2][x3] = 0.f;
        gemm128h(sA, sW1a, acc, warpRow, warpCol, lane);

        // ---- alpha epilogue: pre1 read straight from global (L2-resident) ----
        float p[2][2];
#pragma unroll
        for (int mt = 0; mt < 2; mt++) { p[mt][0] = 0.f; p[mt][1] = 0.f; }
#pragma unroll
        for (int mt = 0; mt < 2; mt++)
#pragma unroll
            for (int j = 0; j < 2; j++) {
                const unsigned* pr =
                    preH + (size_t)sSeg[warpRow * 32 + mt * 16 + g + j * 8] * 64;
#pragma unroll
                for (int nt = 0; nt < 8; nt++) {
                    const int c0 = warpCol * 64 + nt * 8 + 2 * t;
                    unsigned pw = pr[c0 >> 1];
                    float2 pf = __half22float2(*reinterpret_cast<__half2*>(&pw));
                    float x0 = acc[mt][nt][j * 2 + 0] + pf.x + sb1a[c0];
                    float x1 = acc[mt][nt][j * 2 + 1] + pf.y + sb1a[c0 + 1];
                    x0 = (x0 >= 0.f) ? x0 : SLOPE * x0;
                    x1 = (x1 >= 0.f) ? x1 : SLOPE * x1;
                    p[mt][j] += x0 * sw2[c0] + x1 * sw2[c0 + 1];
                }
            }
#pragma unroll
        for (int mt = 0; mt < 2; mt++)
#pragma unroll
            for (int j = 0; j < 2; j++) {
                float v = p[mt][j];
                v += __shfl_xor_sync(0xffffffffu, v, 1);
                v += __shfl_xor_sync(0xffffffffu, v, 2);
                if ((lane & 3) == 0)
                    sPart[(warpRow * 32 + mt * 16 + g + j * 8) * 2 + warpCol] = v;
            }
        __syncthreads();                    // S3: sPart visible
        if (tid < 128) {
            float e = 0.f;
            if (tid < rows) {
                float av = sPart[tid * 2] + sPart[tid * 2 + 1] + ba2v;
                e = expf(av);
                atomicAdd(&g_denom[myseg * 4 + h], e);
            }
            sScale[tid] = e;
        }
        __syncthreads();                    // S4: sScale visible

        // ---- GEMM_m (sA still holds fea) ----
#pragma unroll
        for (int x1 = 0; x1 < 2; x1++)
#pragma unroll
            for (int x2 = 0; x2 < 8; x2++)
#pragma unroll
                for (int x3 = 0; x3 < 4; x3++) acc[x1][x2][x3] = 0.f;
        gemm128h(sA, sW1m, acc, warpRow, warpCol, lane);
        __syncthreads();                    // S5: fea reads done; sA reusable

        // ---- stage e * leaky(acc + b1m) into sA as half2 ----
#pragma unroll
        for (int mt = 0; mt < 2; mt++)
#pragma unroll
            for (int nt = 0; nt < 8; nt++)
#pragma unroll
                for (int ip = 0; ip < 2; ip++) {
                    int row = warpRow * 32 + mt * 16 + g + ip * 8;
                    int c0 = warpCol * 64 + nt * 8 + 2 * t;
                    float sc = sScale[row];
                    float x0 = acc[mt][nt][ip * 2 + 0] + sb1m[c0];
                    float x1 = acc[mt][nt][ip * 2 + 1] + sb1m[c0 + 1];
                    x0 = (x0 >= 0.f) ? x0 : SLOPE * x0;
                    x1 = (x1 >= 0.f) ? x1 : SLOPE * x1;
                    sA[row * LH2 + (c0 >> 1)] = h2pack(x0 * sc, x1 * sc);
                }
        __syncthreads();                    // S6: staging visible

        // ---- segmented reduce: thread = column-pair (64) x row-quarter (4) ----
        {
            const int cp  = tid & 63;
            const int q   = tid >> 6;
            const int r0q = q * 32;
            float a0 = 0.f, a1 = 0.f;
            int cur = sSeg[r0q];
#pragma unroll 4
            for (int r = 0; r < 32; r++) {
                int s = sSeg[r0q + r];
                if (s != cur) {
                    atomicAdd(&Hh[(size_t)cur * 128 + 2 * cp],     a0);
                    atomicAdd(&Hh[(size_t)cur * 128 + 2 * cp + 1], a1);
                    a0 = 0.f; a1 = 0.f;
                    cur = s;
                }
                unsigned pw = sA[(r0q + r) * LH2 + cp];
                float2 pf = __half22float2(*reinterpret_cast<__half2*>(&pw));
                a0 += pf.x; a1 += pf.y;
            }
            atomicAdd(&Hh[(size_t)cur * 128 + 2 * cp],     a0);
            atomicAdd(&Hh[(size_t)cur * 128 + 2 * cp + 1], a1);
        }
        __syncthreads();                    // S7: staging reads done

        const int tn = tile + gridDim.x;
        if (tn < NTILES)
            load_tile_async(sAaddr, g_feah + (size_t)tn * 128 * 64, tid);
    }
}

// ---------------- kernel 2: out = W2 . (H/denom) + b2 * indicator ----------------
__global__ void __launch_bounds__(256, 2)
k_out(const float* __restrict__ Wm2, const float* __restrict__ bm2,
      float* __restrict__ out) {
    extern __shared__ unsigned smem_u[];
    unsigned* sA = smem_u;                 // H tile (fp16, normalized)
    unsigned* sB = sA + 128 * LH2;         // W2
    float* sb2  = (float*)(sB + 128 * LH2);
    float* sInd = sb2 + 128;
    float* sRcp = sInd + 128;

    const int tid  = threadIdx.x;
    const int lane = tid & 31;
    const int warp = tid >> 5;
    const int warpRow = warp >> 1, warpCol = warp & 1;
    const int g = lane >> 2, t = lane & 3;
    const int h  = blockIdx.y;
    const int s0 = blockIdx.x * 128;

    load_w_h(sB, Wm2 + (size_t)h * 128 * 128, 128, tid);
    if (tid < 128) {
        float d = g_denom[(s0 + tid) * 4 + h];
        sb2[tid]  = bm2[h * 128 + tid];
        sInd[tid] = (d > 0.f) ? 1.f : 0.f;
        sRcp[tid] = 1.f / (d + 1e-16f);
    }
    __syncthreads();
    load_rows_scaled(sA, g_H + ((size_t)h * SEGS + s0) * 128, sRcp, tid);
    __syncthreads();

    float acc[2][8][4];
#pragma unroll
    for (int x1 = 0; x1 < 2; x1++)
#pragma unroll
        for (int x2 = 0; x2 < 8; x2++)
#pragma unroll
            for (int x3 = 0; x3 < 4; x3++) acc[x1][x2][x3] = 0.f;
    gemm128h(sA, sB, acc, warpRow, warpCol, lane);

#pragma unroll
    for (int mt = 0; mt < 2; mt++)
#pragma unroll
        for (int nt = 0; nt < 8; nt++)
#pragma unroll
            for (int ip = 0; ip < 2; ip++) {
                int row = warpRow * 32 + mt * 16 + g + ip * 8;
                int c0 = warpCol * 64 + nt * 8 + 2 * t;
                float a = sInd[row];
                float2 v;
                v.x = acc[mt][nt][ip * 2 + 0] * a + sb2[c0] * a;
                v.y = acc[mt][nt][ip * 2 + 1] * a + sb2[c0 + 1] * a;
                *reinterpret_cast<float2*>(
                    out + (size_t)(s0 + row) * 512 + h * 128 + c0) = v;
            }
}

// ---------------- launch ----------------
extern "C" void kernel_launch(void* const* d_in, const int* in_sizes, int n_in,
                              void* d_out, int out_size) {
    (void)in_sizes; (void)n_in; (void)out_size;
    const float* fea = (const float*)d_in[0];
    const float* cry = (const float*)d_in[1];
    const float* Wm1 = (const float*)d_in[2];
    const float* bm1 = (const float*)d_in[3];
    const float* Wm2 = (const float*)d_in[4];
    const float* bm2 = (const float*)d_in[5];
    const float* Wa1 = (const float*)d_in[6];
    const float* ba1 = (const float*)d_in[7];
    const float* Wa2 = (const float*)d_in[8];
    const float* ba2 = (const float*)d_in[9];
    const int*   idx = (const int*)d_in[10];
    float* out = (float*)d_out;

    const size_t smem_pre = (size_t)(2 * 128 * LH2) * 4;
    const size_t smem_am  = (size_t)(3 * 128 * LH2 + 128 + 128 + 128 + 256 + 128 + 128) * 4;
    const size_t smem_out = (size_t)(2 * 128 * LH2 + 128 + 128 + 128) * 4;
    cudaFuncSetAttribute(k_pre, cudaFuncAttributeMaxDynamicSharedMemorySize, (int)smem_pre);
    cudaFuncSetAttribute(k_am,  cudaFuncAttributeMaxDynamicSharedMemorySize, (int)smem_am);
    cudaFuncSetAttribute(k_out, cudaFuncAttributeMaxDynamicSharedMemorySize, (int)smem_out);

    k_init<<<2048, 512>>>(fea);
    k_pre<<<dim3(SEGS / 128, 4), 256, smem_pre>>>(cry, Wa1);
    k_am<<<dim3(74, 4), 256, smem_am>>>(Wa1, ba1, Wa2, ba2, Wm1, bm1, idx);
    k_out<<<dim3(SEGS / 128, 4), 256, smem_out>>>(Wm2, bm2, out);
}